// round 14
// baseline (speedup 1.0000x reference)
#include <cuda_runtime.h>
#include <cuda_bf16.h>
#include <cuda_fp16.h>
#include <cstdint>

#define NN 20000
#define EE 320000
#define FIN 33
#define HF 64
#define NHEADS 4
#define HDMAX 256

// weight arena segment offsets (bf16 elems)
#define W_ENC1 0
#define W_ENC2 4096
#define W_GAT0 8192
#define W_GATM 24576
#define W_GAT4 221184
#define W_TOTAL 237568

// ---------------- scratch ----------------
__device__ __half         g_fh[NN * HDMAX];
__device__ float          g_t[NN * HF];
__device__ __nv_bfloat16  g_ahi[NN * HDMAX];
__device__ __nv_bfloat16  g_alo[NN * HDMAX];
__device__ __nv_bfloat16  g_whi[W_TOTAL];
__device__ __nv_bfloat16  g_wlo[W_TOTAL];
__device__ float  g_el[NN * NHEADS];
__device__ float  g_er[NN * NHEADS];
__device__ double g_bnstat[4 * HF];
__device__ int g_rowptr[NN + 1];
__device__ int g_cnt[NN];
__device__ int g_cnt2[NN];
__device__ int g_srcp[EE];

__device__ __forceinline__ void split_wr(float v, __nv_bfloat16* hi, __nv_bfloat16* lo) {
    __nv_bfloat16 h = __float2bfloat16_rn(v);
    *hi = h;
    *lo = __float2bfloat16_rn(v - __bfloat162float(h));
}

// ---------------- prologue ----------------
__global__ void split_feat_zero(const float* __restrict__ x,
                                __nv_bfloat16* __restrict__ hi,
                                __nv_bfloat16* __restrict__ lo,
                                int* __restrict__ cnt, int* __restrict__ cnt2,
                                double* __restrict__ bs) {
    int idx = blockIdx.x * blockDim.x + threadIdx.x;
    if (idx < NN) { cnt[idx] = 0; cnt2[idx] = 0; }
    if (idx < 4 * HF) bs[idx] = 0.0;
    if (idx >= NN * 64) return;
    int row = idx >> 6, col = idx & 63;
    float v = (col < FIN) ? x[row * FIN + col] : 0.f;
    split_wr(v, &hi[idx], &lo[idx]);
}

__global__ void splitW_all(const float* __restrict__ enc1, const float* __restrict__ enc2,
                           const float* __restrict__ gat0, const float* __restrict__ gatm,
                           const float* __restrict__ gat4,
                           __nv_bfloat16* __restrict__ hi, __nv_bfloat16* __restrict__ lo) {
    int idx = blockIdx.x * blockDim.x + threadIdx.x;
    if (idx >= W_TOTAL) return;
    float v;
    if (idx < W_ENC2) {
        int row = idx >> 6, col = idx & 63;
        v = (row < FIN) ? enc1[row * 64 + col] : 0.f;
    } else if (idx < W_GAT0) {
        v = enc2[idx - W_ENC2];
    } else if (idx < W_GATM) {
        v = gat0[idx - W_GAT0];
    } else if (idx < W_GAT4) {
        v = gatm[idx - W_GATM];
    } else {
        v = gat4[idx - W_GAT4];
    }
    split_wr(v, &hi[idx], &lo[idx]);
}

// ---------------- CSR build ----------------
__global__ void hist_k(const int* __restrict__ dst, int* __restrict__ cnt) {
    int e = blockIdx.x * blockDim.x + threadIdx.x;
    if (e < EE) atomicAdd(&cnt[dst[e]], 1);
}

__global__ void scan_k(const int* __restrict__ cnt, int* __restrict__ rowptr) {
    __shared__ int sh[1024];
    const int t = threadIdx.x;
    const int C = (NN + 1023) / 1024;
    int base = t * C;
    int local[C];
    int s = 0;
#pragma unroll
    for (int i = 0; i < C; i++) {
        int v = (base + i < NN) ? cnt[base + i] : 0;
        local[i] = s; s += v;
    }
    sh[t] = s;
    __syncthreads();
    for (int off = 1; off < 1024; off <<= 1) {
        int v = (t >= off) ? sh[t - off] : 0;
        __syncthreads();
        sh[t] += v;
        __syncthreads();
    }
    int pre = (t > 0) ? sh[t - 1] : 0;
#pragma unroll
    for (int i = 0; i < C; i++)
        if (base + i < NN) rowptr[base + i] = pre + local[i];
    if (t == 1023) rowptr[NN] = sh[1023];
}

__global__ void scatter_k(const int* __restrict__ src, const int* __restrict__ dst,
                          const int* __restrict__ rowptr, int* __restrict__ cnt2,
                          int* __restrict__ srcp) {
    int e = blockIdx.x * blockDim.x + threadIdx.x;
    if (e >= EE) return;
    int d = dst[e];
    int pos = rowptr[d] + atomicAdd(&cnt2[d], 1);
    srcp[pos] = src[e];
}

// ---------------- bf16 3-term GEMM + fused el/er epilogues ----------------
__device__ __forceinline__ void mma16(float* c, const uint32_t* a, const uint32_t* b) {
    asm volatile(
        "mma.sync.aligned.m16n8k16.row.col.f32.bf16.bf16.f32 "
        "{%0,%1,%2,%3}, {%4,%5,%6,%7}, {%8,%9}, {%0,%1,%2,%3};"
        : "+f"(c[0]), "+f"(c[1]), "+f"(c[2]), "+f"(c[3])
        : "r"(a[0]), "r"(a[1]), "r"(a[2]), "r"(a[3]), "r"(b[0]), "r"(b[1]));
}

__device__ __forceinline__ void ldmx4(uint32_t* r, uint32_t addr) {
    asm volatile("ldmatrix.sync.aligned.m8n8.x4.shared.b16 {%0,%1,%2,%3}, [%4];"
                 : "=r"(r[0]), "=r"(r[1]), "=r"(r[2]), "=r"(r[3]) : "r"(addr));
}

__device__ __forceinline__ void ldmx4t(uint32_t* r, uint32_t addr) {
    asm volatile("ldmatrix.sync.aligned.m8n8.x4.trans.shared.b16 {%0,%1,%2,%3}, [%4];"
                 : "=r"(r[0]), "=r"(r[1]), "=r"(r[2]), "=r"(r[3]) : "r"(addr));
}

__device__ __forceinline__ void cpasync16(uint32_t dst, const void* src, int sz) {
    asm volatile("cp.async.cg.shared.global [%0], [%1], 16, %2;"
                 :: "r"(dst), "l"(src), "r"(sz));
}

// TBM: block M tile. ELRM: 0 none; 4 per-head fused el/er (BN=128); 1 single-head (BN=64).
// WF16: write fp16 messages. WF32: write fp32 C.
template <int TBM, int BN, int ELRM, bool WF16, bool WF32>
__global__ void __launch_bounds__(256, TBM == 64 ? 3 : 2)
gemm3(const __nv_bfloat16* __restrict__ Ahi, const __nv_bfloat16* __restrict__ Alo,
      const __nv_bfloat16* __restrict__ Bhi, const __nv_bfloat16* __restrict__ Blo,
      float* __restrict__ C, __half* __restrict__ Fh, int M, int N, int K,
      const float* __restrict__ al, const float* __restrict__ ar,
      float* __restrict__ el, float* __restrict__ er) {
    constexpr int BK = 32;
    constexpr int MT = TBM / 64;
    constexpr int RPW = TBM / 4;
    constexpr int ASTR = 40;
    constexpr int BSTR = BN + 8;
    constexpr int WN = BN / 2, NT = WN / 8;
    constexpr int ATILE = TBM * ASTR;
    constexpr int BTILE = BK * BSTR;
    extern __shared__ __nv_bfloat16 smem[];
    __nv_bfloat16* sA = smem;
    __nv_bfloat16* sB = smem + 4 * ATILE;
    const uint32_t sAu = (uint32_t)__cvta_generic_to_shared(sA);
    const uint32_t sBu = (uint32_t)__cvta_generic_to_shared(sB);

    const int t = threadIdx.x;
    const int warp = t >> 5, lane = t & 31;
    const int wm = warp >> 1, wn = warp & 1;
    const int group = lane >> 2, tig = lane & 3;
    const int bm = blockIdx.y * TBM, bn = blockIdx.x * BN;

    float acc[MT][NT][4];
#pragma unroll
    for (int i = 0; i < MT; i++)
#pragma unroll
        for (int j = 0; j < NT; j++)
#pragma unroll
            for (int q = 0; q < 4; q++) acc[i][j][q] = 0.f;

    auto stage_load = [&](int kt, int stg) {
        const int k0 = kt * BK;
#pragma unroll
        for (int p = 0; p < 2; p++) {
            const __nv_bfloat16* Ag = p ? Alo : Ahi;
#pragma unroll
            for (int i = 0; i < MT; i++) {
                int c = t + i * 256;
                int row = c >> 2, colb = (c & 3) * 8;
                uint32_t dst = sAu + (uint32_t)(((stg * 2 + p) * ATILE + row * ASTR + colb) * 2);
                int grow = bm + row;
                const __nv_bfloat16* src = Ag + (size_t)(grow < M ? grow : 0) * K + k0 + colb;
                cpasync16(dst, src, grow < M ? 16 : 0);
            }
        }
        constexpr int CPROW = BN / 8;
        constexpr int NB = (BK * CPROW) / 256;
#pragma unroll
        for (int p = 0; p < 2; p++) {
            const __nv_bfloat16* Bg = p ? Blo : Bhi;
#pragma unroll
            for (int i = 0; i < NB; i++) {
                int c = t + i * 256;
                int row = c / CPROW, colb = (c % CPROW) * 8;
                uint32_t dst = sBu + (uint32_t)(((stg * 2 + p) * BTILE + row * BSTR + colb) * 2);
                cpasync16(dst, Bg + (size_t)(k0 + row) * N + bn + colb, 16);
            }
        }
    };

    auto compute = [&](int stg) {
#pragma unroll
        for (int ks = 0; ks < 2; ks++) {
            const int k = ks * 16;
            uint32_t Ah[MT][4], Al[MT][4];
#pragma unroll
            for (int mt = 0; mt < MT; mt++) {
                int row = wm * RPW + mt * 16 + (lane & 15);
                int col = k + 8 * (lane >> 4);
                ldmx4(Ah[mt], sAu + (uint32_t)(((stg * 2 + 0) * ATILE + row * ASTR + col) * 2));
                ldmx4(Al[mt], sAu + (uint32_t)(((stg * 2 + 1) * ATILE + row * ASTR + col) * 2));
            }
            const int brow = k + (lane & 7) + 8 * ((lane >> 3) & 1);
#pragma unroll
            for (int ntp = 0; ntp < NT / 2; ntp++) {
                int col = wn * WN + ntp * 16 + 8 * (lane >> 4);
                uint32_t Bh[4], Bl[4];
                ldmx4t(Bh, sBu + (uint32_t)(((stg * 2 + 0) * BTILE + brow * BSTR + col) * 2));
                ldmx4t(Bl, sBu + (uint32_t)(((stg * 2 + 1) * BTILE + brow * BSTR + col) * 2));
#pragma unroll
                for (int hf = 0; hf < 2; hf++) {
                    uint32_t bh2[2] = {Bh[2 * hf], Bh[2 * hf + 1]};
                    uint32_t bl2[2] = {Bl[2 * hf], Bl[2 * hf + 1]};
#pragma unroll
                    for (int mt = 0; mt < MT; mt++) {
                        float* a_ = acc[mt][2 * ntp + hf];
                        mma16(a_, Ah[mt], bh2);
                        mma16(a_, Ah[mt], bl2);
                        mma16(a_, Al[mt], bh2);
                    }
                }
            }
        }
    };

    const int KT = K / BK;
    stage_load(0, 0);
    asm volatile("cp.async.commit_group;");
    for (int kt = 0; kt < KT; kt++) {
        if (kt + 1 < KT) {
            stage_load(kt + 1, (kt + 1) & 1);
            asm volatile("cp.async.commit_group;");
            asm volatile("cp.async.wait_group 1;");
        } else {
            asm volatile("cp.async.wait_group 0;");
        }
        __syncthreads();
        compute(kt & 1);
        __syncthreads();
    }

    // epilogue: stores
#pragma unroll
    for (int mt = 0; mt < MT; mt++) {
        int r0 = bm + wm * RPW + mt * 16 + group;
        int r1 = r0 + 8;
#pragma unroll
        for (int nt = 0; nt < NT; nt++) {
            int c = bn + wn * WN + nt * 8 + tig * 2;
            if constexpr (WF32) {
                if (r0 < M) *(float2*)&C[(size_t)r0 * N + c] = make_float2(acc[mt][nt][0], acc[mt][nt][1]);
                if (r1 < M) *(float2*)&C[(size_t)r1 * N + c] = make_float2(acc[mt][nt][2], acc[mt][nt][3]);
            }
            if constexpr (WF16) {
                if (r0 < M) *(__half2*)&Fh[(size_t)r0 * N + c] = __floats2half2_rn(acc[mt][nt][0], acc[mt][nt][1]);
                if (r1 < M) *(__half2*)&Fh[(size_t)r1 * N + c] = __floats2half2_rn(acc[mt][nt][2], acc[mt][nt][3]);
            }
        }
    }

    if constexpr (ELRM == 4) {
        const int head = blockIdx.x * 2 + wn;
        float pel[MT][2] = {}, per_[MT][2] = {};
#pragma unroll
        for (int nt = 0; nt < NT; nt++) {
            int d = nt * 8 + tig * 2;
            float a0 = al[head * 64 + d], a1 = al[head * 64 + d + 1];
            float b0 = ar[head * 64 + d], b1 = ar[head * 64 + d + 1];
#pragma unroll
            for (int mt = 0; mt < MT; mt++) {
                pel[mt][0]  += acc[mt][nt][0] * a0 + acc[mt][nt][1] * a1;
                pel[mt][1]  += acc[mt][nt][2] * a0 + acc[mt][nt][3] * a1;
                per_[mt][0] += acc[mt][nt][0] * b0 + acc[mt][nt][1] * b1;
                per_[mt][1] += acc[mt][nt][2] * b0 + acc[mt][nt][3] * b1;
            }
        }
#pragma unroll
        for (int off = 1; off <= 2; off <<= 1) {
#pragma unroll
            for (int mt = 0; mt < MT; mt++)
#pragma unroll
                for (int rr = 0; rr < 2; rr++) {
                    pel[mt][rr]  += __shfl_xor_sync(0xffffffffu, pel[mt][rr], off);
                    per_[mt][rr] += __shfl_xor_sync(0xffffffffu, per_[mt][rr], off);
                }
        }
        if (tig == 0) {
#pragma unroll
            for (int mt = 0; mt < MT; mt++) {
                int r0 = bm + wm * RPW + mt * 16 + group;
                if (r0 < M)     { el[r0 * 4 + head] = pel[mt][0]; er[r0 * 4 + head] = per_[mt][0]; }
                if (r0 + 8 < M) { el[(r0 + 8) * 4 + head] = pel[mt][1]; er[(r0 + 8) * 4 + head] = per_[mt][1]; }
            }
        }
    }

    if constexpr (ELRM == 1) {
        float* sf = (float*)smem;
        float pel[MT][2] = {}, per_[MT][2] = {};
#pragma unroll
        for (int nt = 0; nt < NT; nt++) {
            int c = wn * WN + nt * 8 + tig * 2;
            float a0 = al[c], a1 = al[c + 1];
            float b0 = ar[c], b1 = ar[c + 1];
#pragma unroll
            for (int mt = 0; mt < MT; mt++) {
                pel[mt][0]  += acc[mt][nt][0] * a0 + acc[mt][nt][1] * a1;
                pel[mt][1]  += acc[mt][nt][2] * a0 + acc[mt][nt][3] * a1;
                per_[mt][0] += acc[mt][nt][0] * b0 + acc[mt][nt][1] * b1;
                per_[mt][1] += acc[mt][nt][2] * b0 + acc[mt][nt][3] * b1;
            }
        }
#pragma unroll
        for (int off = 1; off <= 2; off <<= 1) {
#pragma unroll
            for (int mt = 0; mt < MT; mt++)
#pragma unroll
                for (int rr = 0; rr < 2; rr++) {
                    pel[mt][rr]  += __shfl_xor_sync(0xffffffffu, pel[mt][rr], off);
                    per_[mt][rr] += __shfl_xor_sync(0xffffffffu, per_[mt][rr], off);
                }
        }
        __syncthreads();
        if (tig == 0) {
#pragma unroll
            for (int mt = 0; mt < MT; mt++)
#pragma unroll
                for (int rr = 0; rr < 2; rr++) {
                    int lrow = wm * RPW + mt * 16 + group + rr * 8;
                    sf[wn * (TBM * 2) + lrow * 2]     = pel[mt][rr];
                    sf[wn * (TBM * 2) + lrow * 2 + 1] = per_[mt][rr];
                }
        }
        __syncthreads();
        if (t < TBM) {
            int grow = bm + t;
            if (grow < M) {
                el[grow] = sf[t * 2]     + sf[TBM * 2 + t * 2];
                er[grow] = sf[t * 2 + 1] + sf[TBM * 2 + t * 2 + 1];
            }
        }
    }
}

// ---------------- BatchNorm ----------------
__global__ void bn_stats(const float* __restrict__ x, double* sum, double* sq, int M) {
    const int col = threadIdx.x & 63;
    const int rlane = threadIdx.x >> 6;
    double s = 0, q = 0;
    for (int r = blockIdx.x * 4 + rlane; r < M; r += gridDim.x * 4) {
        double v = x[(size_t)r * HF + col];
        s += v; q += v * v;
    }
    __shared__ double sh[2][256];
    sh[0][threadIdx.x] = s; sh[1][threadIdx.x] = q;
    __syncthreads();
    if (rlane == 0) {
#pragma unroll
        for (int i = 1; i < 4; i++) { s += sh[0][i * 64 + col]; q += sh[1][i * 64 + col]; }
        atomicAdd(&sum[col], s);
        atomicAdd(&sq[col], q);
    }
}

__global__ void bn_apply_bf(const float* __restrict__ x, const double* __restrict__ sum,
                            const double* __restrict__ sq, const float* __restrict__ g,
                            const float* __restrict__ b,
                            __nv_bfloat16* __restrict__ hi, __nv_bfloat16* __restrict__ lo,
                            int M) {
    int idx = blockIdx.x * blockDim.x + threadIdx.x;
    if (idx >= M * HF) return;
    int c = idx & 63;
    double mu = sum[c] / M;
    double var = sq[c] / M - mu * mu;
    float inv = rsqrtf((float)var + 1e-5f);
    float y = ((float)(x[idx] - mu)) * inv * g[c] + b[c];
    y = y > 0.f ? y : 0.01f * y;
    split_wr(y, &hi[idx], &lo[idx]);
}

// ---------------- H=4 GAT: 2 warps per node, online softmax + state merge ----------
__global__ void __launch_bounds__(256)
gat_agg4x2(const __half* __restrict__ fh, const float* __restrict__ el,
           const float* __restrict__ er, const int* __restrict__ rowptr,
           const int* __restrict__ srcp, const float* __restrict__ bias,
           __nv_bfloat16* __restrict__ ohi, __nv_bfloat16* __restrict__ olo) {
    constexpr int HD = 256, CPL = 8;
    __shared__ float sacc[4][256];
    __shared__ float sm_[4][32];
    __shared__ float sd_[4][32];
    const int w = threadIdx.x >> 5, lane = threadIdx.x & 31;
    const int p = w >> 1, half = w & 1;
    const int node = blockIdx.x * 4 + p;            // NN % 4 == 0
    const int h = lane >> 3;
    const int c0 = lane * CPL;

    const int s0 = rowptr[node], s1 = rowptr[node + 1];
    const int n = s1 - s0;
    const int chalf = (n + 1) >> 1;
    const int b0 = s0 + half * chalf;
    const int b1 = half ? s1 : s0 + chalf;

    float m = -3.4e38f, den = 0.f;
    float acc[CPL] = {};
    if (b0 < b1) {
        const float ern = er[node * 4 + h];
        const int sfb = __ldg(&srcp[b0]);
        for (int e = b0; e < b1; e += 4) {
            int sx[4];
#pragma unroll
            for (int j = 0; j < 4; j++)
                sx[j] = (e + j) < b1 ? __ldg(&srcp[e + j]) : sfb;
            float vv[4];
#pragma unroll
            for (int j = 0; j < 4; j++) {
                float v = __ldg(&el[sx[j] * 4 + h]) + ern;
                v = v > 0.f ? v : 0.2f * v;
                vv[j] = (e + j) < b1 ? v : -3.4e38f;
            }
            uint4 raw[4];
#pragma unroll
            for (int j = 0; j < 4; j++)
                raw[j] = *(const uint4*)(fh + (size_t)sx[j] * HD + c0);
            float bmax = fmaxf(fmaxf(vv[0], vv[1]), fmaxf(vv[2], vv[3]));
            if (bmax > m) {
                float sc = __expf(m - bmax);
                den *= sc;
#pragma unroll
                for (int i = 0; i < CPL; i++) acc[i] *= sc;
                m = bmax;
            }
#pragma unroll
            for (int j = 0; j < 4; j++) {
                float ex = __expf(vv[j] - m);
                den += ex;
                const __half2* hp = (const __half2*)&raw[j];
#pragma unroll
                for (int q = 0; q < 4; q++) {
                    float2 mv = __half22float2(hp[q]);
                    acc[2 * q]     = fmaf(ex, mv.x, acc[2 * q]);
                    acc[2 * q + 1] = fmaf(ex, mv.y, acc[2 * q + 1]);
                }
            }
        }
    }
    if (half == 0) {
#pragma unroll
        for (int i = 0; i < CPL; i++) sacc[p][c0 + i] = acc[i];
        sm_[p][lane] = m;
        sd_[p][lane] = den;
    }
    __syncthreads();
    if (half == 1) {
        float outv[CPL];
        if (n == 0) {
#pragma unroll
            for (int i = 0; i < CPL; i++) {
                float y = bias[c0 + i];
                outv[i] = y > 0.f ? y : 0.01f * y;
            }
        } else {
            float m0 = sm_[p][lane], d0 = sd_[p][lane];
            float M_ = fmaxf(m0, m);
            float sc0 = __expf(m0 - M_), sc1 = __expf(m - M_);
            float dt = d0 * sc0 + den * sc1;
            float inv = 1.f / dt;
#pragma unroll
            for (int i = 0; i < CPL; i++) {
                float a = sacc[p][c0 + i] * sc0 + acc[i] * sc1;
                float y = a * inv + bias[c0 + i];
                outv[i] = y > 0.f ? y : 0.01f * y;
            }
        }
        __nv_bfloat162 hp2[CPL / 2], lp2[CPL / 2];
#pragma unroll
        for (int j = 0; j < CPL / 2; j++) {
            float x = outv[2 * j], y = outv[2 * j + 1];
            __nv_bfloat162 h2 = __floats2bfloat162_rn(x, y);
            hp2[j] = h2;
            lp2[j] = __floats2bfloat162_rn(x - __bfloat162float(h2.x),
                                           y - __bfloat162float(h2.y));
        }
        size_t off = (size_t)node * HD + c0;
        *(uint4*)&ohi[off] = *(uint4*)hp2;
        *(uint4*)&olo[off] = *(uint4*)lp2;
    }
}

// ---------------- H=1 GAT (gat4): warp per node + fused fc ----------------
__global__ void gat_agg1fc(const __half* __restrict__ fh, const float* __restrict__ el,
                           const float* __restrict__ er, const int* __restrict__ rowptr,
                           const int* __restrict__ srcp, const float* __restrict__ bias,
                           const float* __restrict__ fcW, const float* __restrict__ fcb,
                           float* __restrict__ out) {
    constexpr int HD = 64, CPL = 2;
    int node = (blockIdx.x * blockDim.x + threadIdx.x) >> 5;
    if (node >= NN) return;
    int lane = threadIdx.x & 31;
    int c0 = lane * CPL;
    int s0 = rowptr[node], s1 = rowptr[node + 1];
    float outv[CPL];
    if (s0 == s1) {
#pragma unroll
        for (int i = 0; i < CPL; i++) {
            float y = bias[c0 + i];
            outv[i] = y > 0.f ? y : 0.01f * y;
        }
    } else {
        float ern = er[node];
        int sfb = __ldg(&srcp[s0]);
        float m = -3.4e38f, den = 0.f;
        float acc[CPL] = {};
        for (int e = s0; e < s1; e += 4) {
            int sx[4];
#pragma unroll
            for (int j = 0; j < 4; j++)
                sx[j] = (e + j) < s1 ? __ldg(&srcp[e + j]) : sfb;
            float vv[4];
#pragma unroll
            for (int j = 0; j < 4; j++) {
                float v = __ldg(&el[sx[j]]) + ern;
                v = v > 0.f ? v : 0.2f * v;
                vv[j] = (e + j) < s1 ? v : -3.4e38f;
            }
            uint32_t raw[4];
#pragma unroll
            for (int j = 0; j < 4; j++)
                raw[j] = *(const uint32_t*)(fh + (size_t)sx[j] * HD + c0);
            float bmax = fmaxf(fmaxf(vv[0], vv[1]), fmaxf(vv[2], vv[3]));
            if (bmax > m) {
                float sc = __expf(m - bmax);
                den *= sc;
#pragma unroll
                for (int i = 0; i < CPL; i++) acc[i] *= sc;
                m = bmax;
            }
#pragma unroll
            for (int j = 0; j < 4; j++) {
                float ex = __expf(vv[j] - m);
                den += ex;
                float2 mv = __half22float2(*(const __half2*)&raw[j]);
                acc[0] = fmaf(ex, mv.x, acc[0]);
                acc[1] = fmaf(ex, mv.y, acc[1]);
            }
        }
        float inv = 1.f / den;
#pragma unroll
        for (int i = 0; i < CPL; i++) {
            float y = acc[i] * inv + bias[c0 + i];
            outv[i] = y > 0.f ? y : 0.01f * y;
        }
    }
    float p0 = outv[0] * fcW[c0 * 2]     + outv[1] * fcW[(c0 + 1) * 2];
    float p1 = outv[0] * fcW[c0 * 2 + 1] + outv[1] * fcW[(c0 + 1) * 2 + 1];
#pragma unroll
    for (int off = 16; off; off >>= 1) {
        p0 += __shfl_xor_sync(0xffffffffu, p0, off);
        p1 += __shfl_xor_sync(0xffffffffu, p1, off);
    }
    if (lane == 0) {
        out[node * 2]     = p0 + fcb[0];
        out[node * 2 + 1] = p1 + fcb[1];
    }
}

// ---------------- host ----------------
static inline int cdiv(long a, long b) { return (int)((a + b - 1) / b); }

extern "C" void kernel_launch(void* const* d_in, const int* in_sizes, int n_in,
                              void* d_out, int out_size) {
    const float* feat    = (const float*)d_in[0];
    const int*   src     = (const int*)  d_in[1];
    const int*   dst     = (const int*)  d_in[2];
    const float* enc1_W  = (const float*)d_in[3];
    const float* bn1_g   = (const float*)d_in[5];
    const float* bn1_b   = (const float*)d_in[6];
    const float* enc2_W  = (const float*)d_in[7];
    const float* bn2_g   = (const float*)d_in[9];
    const float* bn2_b   = (const float*)d_in[10];
    const float* gat0_W  = (const float*)d_in[11];
    const float* gat0_al = (const float*)d_in[12];
    const float* gat0_ar = (const float*)d_in[13];
    const float* gat0_b  = (const float*)d_in[14];
    const float* gatm_W  = (const float*)d_in[15];
    const float* gatm_al = (const float*)d_in[16];
    const float* gatm_ar = (const float*)d_in[17];
    const float* gatm_b  = (const float*)d_in[18];
    const float* gat4_W  = (const float*)d_in[19];
    const float* gat4_al = (const float*)d_in[20];
    const float* gat4_ar = (const float*)d_in[21];
    const float* gat4_b  = (const float*)d_in[22];
    const float* fc_W    = (const float*)d_in[23];
    const float* fc_b    = (const float*)d_in[24];
    float* out = (float*)d_out;

    float *tmp, *el, *er;
    __half* fh;
    __nv_bfloat16 *ahi, *alo, *whi, *wlo;
    double *bnstat;
    int *rowptr, *cnt, *cnt2, *srcp;
    cudaGetSymbolAddress((void**)&fh,     g_fh);
    cudaGetSymbolAddress((void**)&tmp,    g_t);
    cudaGetSymbolAddress((void**)&ahi,    g_ahi);
    cudaGetSymbolAddress((void**)&alo,    g_alo);
    cudaGetSymbolAddress((void**)&whi,    g_whi);
    cudaGetSymbolAddress((void**)&wlo,    g_wlo);
    cudaGetSymbolAddress((void**)&el,     g_el);
    cudaGetSymbolAddress((void**)&er,     g_er);
    cudaGetSymbolAddress((void**)&bnstat, g_bnstat);
    cudaGetSymbolAddress((void**)&rowptr, g_rowptr);
    cudaGetSymbolAddress((void**)&cnt,    g_cnt);
    cudaGetSymbolAddress((void**)&cnt2,   g_cnt2);
    cudaGetSymbolAddress((void**)&srcp,   g_srcp);

    const int SM64_128 = (4 * 64 * 40 + 4 * 32 * (128 + 8)) * 2;  // 55296
    const int SM64     = (4 * 64 * 40 + 4 * 32 * (64 + 8)) * 2;   // 38912
    cudaFuncSetAttribute((const void*)gemm3<64, 128, 4, true, false>,
                         cudaFuncAttributeMaxDynamicSharedMemorySize, SM64_128);
    cudaFuncSetAttribute((const void*)gemm3<64, 64, 0, false, true>,
                         cudaFuncAttributeMaxDynamicSharedMemorySize, SM64);
    cudaFuncSetAttribute((const void*)gemm3<64, 64, 1, true, false>,
                         cudaFuncAttributeMaxDynamicSharedMemorySize, SM64);

    const int MB64 = cdiv(NN, 64);   // 313
    const int WARP_BLOCKS = cdiv((long)NN * 32, 256);
    const int PAIR_BLOCKS = NN / 4;  // 5000 (2 warps/node, 4 nodes/block)

    // ---- prologue ----
    split_feat_zero<<<cdiv((long)NN * 64, 256), 256>>>(feat, ahi, alo, cnt, cnt2, bnstat);
    splitW_all<<<cdiv(W_TOTAL, 256), 256>>>(enc1_W, enc2_W, gat0_W, gatm_W, gat4_W, whi, wlo);
    hist_k<<<cdiv(EE, 256), 256>>>(dst, cnt);
    gemm3<64, 64, 0, false, true><<<dim3(1, MB64), 256, SM64>>>(
        ahi, alo, whi + W_ENC1, wlo + W_ENC1, tmp, nullptr, NN, HF, 64,
        nullptr, nullptr, nullptr, nullptr);  // launch idx 3 (ncu slot)
    scan_k<<<1, 1024>>>(cnt, rowptr);
    scatter_k<<<cdiv(EE, 256), 256>>>(src, dst, rowptr, cnt2, srcp);

    // ---- encoder (biases cancel inside training-mode BN) ----
    bn_stats<<<120, 256>>>(tmp, bnstat, bnstat + HF, NN);
    bn_apply_bf<<<cdiv((long)NN * HF, 256), 256>>>(tmp, bnstat, bnstat + HF,
                                                   bn1_g, bn1_b, ahi, alo, NN);
    gemm3<64, 64, 0, false, true><<<dim3(1, MB64), 256, SM64>>>(
        ahi, alo, whi + W_ENC2, wlo + W_ENC2, tmp, nullptr, NN, HF, 64,
        nullptr, nullptr, nullptr, nullptr);
    bn_stats<<<120, 256>>>(tmp, bnstat + 2 * HF, bnstat + 3 * HF, NN);
    bn_apply_bf<<<cdiv((long)NN * HF, 256), 256>>>(tmp, bnstat + 2 * HF, bnstat + 3 * HF,
                                                   bn2_g, bn2_b, ahi, alo, NN);

    // ---- GAT stack ----
    gemm3<64, 128, 4, true, false><<<dim3(2, MB64), 256, SM64_128>>>(
        ahi, alo, whi + W_GAT0, wlo + W_GAT0, nullptr, fh, NN, HDMAX, 64,
        gat0_al, gat0_ar, el, er);
    gat_agg4x2<<<PAIR_BLOCKS, 256>>>(fh, el, er, rowptr, srcp, gat0_b, ahi, alo);
    for (int i = 0; i < 3; i++) {
        gemm3<64, 128, 4, true, false><<<dim3(2, MB64), 256, SM64_128>>>(
            ahi, alo, whi + W_GATM + (size_t)i * HDMAX * HDMAX,
            wlo + W_GATM + (size_t)i * HDMAX * HDMAX, nullptr, fh, NN, HDMAX, HDMAX,
            gatm_al + i * NHEADS * HF, gatm_ar + i * NHEADS * HF, el, er);
        gat_agg4x2<<<PAIR_BLOCKS, 256>>>(fh, el, er, rowptr, srcp,
                                         gatm_b + i * HDMAX, ahi, alo);
    }
    gemm3<64, 64, 1, true, false><<<dim3(1, MB64), 256, SM64>>>(
        ahi, alo, whi + W_GAT4, wlo + W_GAT4, nullptr, fh, NN, HF, HDMAX,
        gat4_al, gat4_ar, el, er);
    gat_agg1fc<<<WARP_BLOCKS, 256>>>(fh, el, er, rowptr, srcp, gat4_b, fc_W, fc_b, out);
}

// round 15
// speedup vs baseline: 1.0620x; 1.0620x over previous
#include <cuda_runtime.h>
#include <cuda_bf16.h>
#include <cuda_fp16.h>
#include <cstdint>

#define NN 20000
#define EE 320000
#define FIN 33
#define HF 64
#define NHEADS 4
#define HDMAX 256

// weight arena segment offsets (bf16 elems)
#define W_ENC1 0
#define W_ENC2 4096
#define W_GAT0 8192
#define W_GATM 24576
#define W_GAT4 221184
#define W_TOTAL 237568

// ---------------- scratch ----------------
__device__ __half         g_fh[NN * HDMAX];
__device__ float          g_t[NN * HF];
__device__ __nv_bfloat16  g_ahi[NN * HDMAX];
__device__ __nv_bfloat16  g_alo[NN * HDMAX];
__device__ __nv_bfloat16  g_whi[W_TOTAL];
__device__ __nv_bfloat16  g_wlo[W_TOTAL];
__device__ float  g_el[NN * NHEADS];
__device__ float  g_er[NN * NHEADS];
__device__ double g_bnstat[4 * HF];
__device__ int g_rowptr[NN + 1];
__device__ int g_cnt[NN];
__device__ int g_cnt2[NN];
__device__ int g_srcp[EE];

__device__ __forceinline__ void split_wr(float v, __nv_bfloat16* hi, __nv_bfloat16* lo) {
    __nv_bfloat16 h = __float2bfloat16_rn(v);
    *hi = h;
    *lo = __float2bfloat16_rn(v - __bfloat162float(h));
}

// ---------------- prologue ----------------
__global__ void split_feat_zero(const float* __restrict__ x,
                                __nv_bfloat16* __restrict__ hi,
                                __nv_bfloat16* __restrict__ lo,
                                int* __restrict__ cnt, int* __restrict__ cnt2,
                                double* __restrict__ bs) {
    int idx = blockIdx.x * blockDim.x + threadIdx.x;
    if (idx < NN) { cnt[idx] = 0; cnt2[idx] = 0; }
    if (idx < 4 * HF) bs[idx] = 0.0;
    if (idx >= NN * 64) return;
    int row = idx >> 6, col = idx & 63;
    float v = (col < FIN) ? x[row * FIN + col] : 0.f;
    split_wr(v, &hi[idx], &lo[idx]);
}

__global__ void splitW_all(const float* __restrict__ enc1, const float* __restrict__ enc2,
                           const float* __restrict__ gat0, const float* __restrict__ gatm,
                           const float* __restrict__ gat4,
                           __nv_bfloat16* __restrict__ hi, __nv_bfloat16* __restrict__ lo) {
    int idx = blockIdx.x * blockDim.x + threadIdx.x;
    if (idx >= W_TOTAL) return;
    float v;
    if (idx < W_ENC2) {
        int row = idx >> 6, col = idx & 63;
        v = (row < FIN) ? enc1[row * 64 + col] : 0.f;
    } else if (idx < W_GAT0) {
        v = enc2[idx - W_ENC2];
    } else if (idx < W_GATM) {
        v = gat0[idx - W_GAT0];
    } else if (idx < W_GAT4) {
        v = gatm[idx - W_GATM];
    } else {
        v = gat4[idx - W_GAT4];
    }
    split_wr(v, &hi[idx], &lo[idx]);
}

// ---------------- CSR build ----------------
__global__ void hist_k(const int* __restrict__ dst, int* __restrict__ cnt) {
    int e = blockIdx.x * blockDim.x + threadIdx.x;
    if (e < EE) atomicAdd(&cnt[dst[e]], 1);
}

__global__ void scan_k(const int* __restrict__ cnt, int* __restrict__ rowptr) {
    __shared__ int sh[1024];
    const int t = threadIdx.x;
    const int C = (NN + 1023) / 1024;
    int base = t * C;
    int local[C];
    int s = 0;
#pragma unroll
    for (int i = 0; i < C; i++) {
        int v = (base + i < NN) ? cnt[base + i] : 0;
        local[i] = s; s += v;
    }
    sh[t] = s;
    __syncthreads();
    for (int off = 1; off < 1024; off <<= 1) {
        int v = (t >= off) ? sh[t - off] : 0;
        __syncthreads();
        sh[t] += v;
        __syncthreads();
    }
    int pre = (t > 0) ? sh[t - 1] : 0;
#pragma unroll
    for (int i = 0; i < C; i++)
        if (base + i < NN) rowptr[base + i] = pre + local[i];
    if (t == 1023) rowptr[NN] = sh[1023];
}

__global__ void scatter_k(const int* __restrict__ src, const int* __restrict__ dst,
                          const int* __restrict__ rowptr, int* __restrict__ cnt2,
                          int* __restrict__ srcp) {
    int e = blockIdx.x * blockDim.x + threadIdx.x;
    if (e >= EE) return;
    int d = dst[e];
    int pos = rowptr[d] + atomicAdd(&cnt2[d], 1);
    srcp[pos] = src[e];
}

// ---------------- bf16 3-term GEMM + fused el/er epilogues ----------------
__device__ __forceinline__ void mma16(float* c, const uint32_t* a, const uint32_t* b) {
    asm volatile(
        "mma.sync.aligned.m16n8k16.row.col.f32.bf16.bf16.f32 "
        "{%0,%1,%2,%3}, {%4,%5,%6,%7}, {%8,%9}, {%0,%1,%2,%3};"
        : "+f"(c[0]), "+f"(c[1]), "+f"(c[2]), "+f"(c[3])
        : "r"(a[0]), "r"(a[1]), "r"(a[2]), "r"(a[3]), "r"(b[0]), "r"(b[1]));
}

__device__ __forceinline__ void ldmx4(uint32_t* r, uint32_t addr) {
    asm volatile("ldmatrix.sync.aligned.m8n8.x4.shared.b16 {%0,%1,%2,%3}, [%4];"
                 : "=r"(r[0]), "=r"(r[1]), "=r"(r[2]), "=r"(r[3]) : "r"(addr));
}

__device__ __forceinline__ void ldmx4t(uint32_t* r, uint32_t addr) {
    asm volatile("ldmatrix.sync.aligned.m8n8.x4.trans.shared.b16 {%0,%1,%2,%3}, [%4];"
                 : "=r"(r[0]), "=r"(r[1]), "=r"(r[2]), "=r"(r[3]) : "r"(addr));
}

__device__ __forceinline__ void cpasync16(uint32_t dst, const void* src, int sz) {
    asm volatile("cp.async.cg.shared.global [%0], [%1], 16, %2;"
                 :: "r"(dst), "l"(src), "r"(sz));
}

// TBM: block M tile. ELRM: 0 none; 4 per-head fused el/er (BN=128); 1 single-head (BN=64).
// WF16: write fp16 messages. WF32: write fp32 C.
template <int TBM, int BN, int ELRM, bool WF16, bool WF32>
__global__ void __launch_bounds__(256, TBM == 64 ? 3 : 2)
gemm3(const __nv_bfloat16* __restrict__ Ahi, const __nv_bfloat16* __restrict__ Alo,
      const __nv_bfloat16* __restrict__ Bhi, const __nv_bfloat16* __restrict__ Blo,
      float* __restrict__ C, __half* __restrict__ Fh, int M, int N, int K,
      const float* __restrict__ al, const float* __restrict__ ar,
      float* __restrict__ el, float* __restrict__ er) {
    constexpr int BK = 32;
    constexpr int MT = TBM / 64;
    constexpr int RPW = TBM / 4;
    constexpr int ASTR = 40;
    constexpr int BSTR = BN + 8;
    constexpr int WN = BN / 2, NT = WN / 8;
    constexpr int ATILE = TBM * ASTR;
    constexpr int BTILE = BK * BSTR;
    extern __shared__ __nv_bfloat16 smem[];
    __nv_bfloat16* sA = smem;
    __nv_bfloat16* sB = smem + 4 * ATILE;
    const uint32_t sAu = (uint32_t)__cvta_generic_to_shared(sA);
    const uint32_t sBu = (uint32_t)__cvta_generic_to_shared(sB);

    const int t = threadIdx.x;
    const int warp = t >> 5, lane = t & 31;
    const int wm = warp >> 1, wn = warp & 1;
    const int group = lane >> 2, tig = lane & 3;
    const int bm = blockIdx.y * TBM, bn = blockIdx.x * BN;

    float acc[MT][NT][4];
#pragma unroll
    for (int i = 0; i < MT; i++)
#pragma unroll
        for (int j = 0; j < NT; j++)
#pragma unroll
            for (int q = 0; q < 4; q++) acc[i][j][q] = 0.f;

    auto stage_load = [&](int kt, int stg) {
        const int k0 = kt * BK;
#pragma unroll
        for (int p = 0; p < 2; p++) {
            const __nv_bfloat16* Ag = p ? Alo : Ahi;
#pragma unroll
            for (int i = 0; i < MT; i++) {
                int c = t + i * 256;
                int row = c >> 2, colb = (c & 3) * 8;
                uint32_t dst = sAu + (uint32_t)(((stg * 2 + p) * ATILE + row * ASTR + colb) * 2);
                int grow = bm + row;
                const __nv_bfloat16* src = Ag + (size_t)(grow < M ? grow : 0) * K + k0 + colb;
                cpasync16(dst, src, grow < M ? 16 : 0);
            }
        }
        constexpr int CPROW = BN / 8;
        constexpr int NB = (BK * CPROW) / 256;
#pragma unroll
        for (int p = 0; p < 2; p++) {
            const __nv_bfloat16* Bg = p ? Blo : Bhi;
#pragma unroll
            for (int i = 0; i < NB; i++) {
                int c = t + i * 256;
                int row = c / CPROW, colb = (c % CPROW) * 8;
                uint32_t dst = sBu + (uint32_t)(((stg * 2 + p) * BTILE + row * BSTR + colb) * 2);
                cpasync16(dst, Bg + (size_t)(k0 + row) * N + bn + colb, 16);
            }
        }
    };

    auto compute = [&](int stg) {
#pragma unroll
        for (int ks = 0; ks < 2; ks++) {
            const int k = ks * 16;
            uint32_t Ah[MT][4], Al[MT][4];
#pragma unroll
            for (int mt = 0; mt < MT; mt++) {
                int row = wm * RPW + mt * 16 + (lane & 15);
                int col = k + 8 * (lane >> 4);
                ldmx4(Ah[mt], sAu + (uint32_t)(((stg * 2 + 0) * ATILE + row * ASTR + col) * 2));
                ldmx4(Al[mt], sAu + (uint32_t)(((stg * 2 + 1) * ATILE + row * ASTR + col) * 2));
            }
            const int brow = k + (lane & 7) + 8 * ((lane >> 3) & 1);
#pragma unroll
            for (int ntp = 0; ntp < NT / 2; ntp++) {
                int col = wn * WN + ntp * 16 + 8 * (lane >> 4);
                uint32_t Bh[4], Bl[4];
                ldmx4t(Bh, sBu + (uint32_t)(((stg * 2 + 0) * BTILE + brow * BSTR + col) * 2));
                ldmx4t(Bl, sBu + (uint32_t)(((stg * 2 + 1) * BTILE + brow * BSTR + col) * 2));
#pragma unroll
                for (int hf = 0; hf < 2; hf++) {
                    uint32_t bh2[2] = {Bh[2 * hf], Bh[2 * hf + 1]};
                    uint32_t bl2[2] = {Bl[2 * hf], Bl[2 * hf + 1]};
#pragma unroll
                    for (int mt = 0; mt < MT; mt++) {
                        float* a_ = acc[mt][2 * ntp + hf];
                        mma16(a_, Ah[mt], bh2);
                        mma16(a_, Ah[mt], bl2);
                        mma16(a_, Al[mt], bh2);
                    }
                }
            }
        }
    };

    const int KT = K / BK;
    stage_load(0, 0);
    asm volatile("cp.async.commit_group;");
    for (int kt = 0; kt < KT; kt++) {
        if (kt + 1 < KT) {
            stage_load(kt + 1, (kt + 1) & 1);
            asm volatile("cp.async.commit_group;");
            asm volatile("cp.async.wait_group 1;");
        } else {
            asm volatile("cp.async.wait_group 0;");
        }
        __syncthreads();
        compute(kt & 1);
        __syncthreads();
    }

    // epilogue: stores
#pragma unroll
    for (int mt = 0; mt < MT; mt++) {
        int r0 = bm + wm * RPW + mt * 16 + group;
        int r1 = r0 + 8;
#pragma unroll
        for (int nt = 0; nt < NT; nt++) {
            int c = bn + wn * WN + nt * 8 + tig * 2;
            if constexpr (WF32) {
                if (r0 < M) *(float2*)&C[(size_t)r0 * N + c] = make_float2(acc[mt][nt][0], acc[mt][nt][1]);
                if (r1 < M) *(float2*)&C[(size_t)r1 * N + c] = make_float2(acc[mt][nt][2], acc[mt][nt][3]);
            }
            if constexpr (WF16) {
                if (r0 < M) *(__half2*)&Fh[(size_t)r0 * N + c] = __floats2half2_rn(acc[mt][nt][0], acc[mt][nt][1]);
                if (r1 < M) *(__half2*)&Fh[(size_t)r1 * N + c] = __floats2half2_rn(acc[mt][nt][2], acc[mt][nt][3]);
            }
        }
    }

    if constexpr (ELRM == 4) {
        const int head = blockIdx.x * 2 + wn;
        float pel[MT][2] = {}, per_[MT][2] = {};
#pragma unroll
        for (int nt = 0; nt < NT; nt++) {
            int d = nt * 8 + tig * 2;
            float a0 = al[head * 64 + d], a1 = al[head * 64 + d + 1];
            float b0 = ar[head * 64 + d], b1 = ar[head * 64 + d + 1];
#pragma unroll
            for (int mt = 0; mt < MT; mt++) {
                pel[mt][0]  += acc[mt][nt][0] * a0 + acc[mt][nt][1] * a1;
                pel[mt][1]  += acc[mt][nt][2] * a0 + acc[mt][nt][3] * a1;
                per_[mt][0] += acc[mt][nt][0] * b0 + acc[mt][nt][1] * b1;
                per_[mt][1] += acc[mt][nt][2] * b0 + acc[mt][nt][3] * b1;
            }
        }
#pragma unroll
        for (int off = 1; off <= 2; off <<= 1) {
#pragma unroll
            for (int mt = 0; mt < MT; mt++)
#pragma unroll
                for (int rr = 0; rr < 2; rr++) {
                    pel[mt][rr]  += __shfl_xor_sync(0xffffffffu, pel[mt][rr], off);
                    per_[mt][rr] += __shfl_xor_sync(0xffffffffu, per_[mt][rr], off);
                }
        }
        if (tig == 0) {
#pragma unroll
            for (int mt = 0; mt < MT; mt++) {
                int r0 = bm + wm * RPW + mt * 16 + group;
                if (r0 < M)     { el[r0 * 4 + head] = pel[mt][0]; er[r0 * 4 + head] = per_[mt][0]; }
                if (r0 + 8 < M) { el[(r0 + 8) * 4 + head] = pel[mt][1]; er[(r0 + 8) * 4 + head] = per_[mt][1]; }
            }
        }
    }

    if constexpr (ELRM == 1) {
        float* sf = (float*)smem;
        float pel[MT][2] = {}, per_[MT][2] = {};
#pragma unroll
        for (int nt = 0; nt < NT; nt++) {
            int c = wn * WN + nt * 8 + tig * 2;
            float a0 = al[c], a1 = al[c + 1];
            float b0 = ar[c], b1 = ar[c + 1];
#pragma unroll
            for (int mt = 0; mt < MT; mt++) {
                pel[mt][0]  += acc[mt][nt][0] * a0 + acc[mt][nt][1] * a1;
                pel[mt][1]  += acc[mt][nt][2] * a0 + acc[mt][nt][3] * a1;
                per_[mt][0] += acc[mt][nt][0] * b0 + acc[mt][nt][1] * b1;
                per_[mt][1] += acc[mt][nt][2] * b0 + acc[mt][nt][3] * b1;
            }
        }
#pragma unroll
        for (int off = 1; off <= 2; off <<= 1) {
#pragma unroll
            for (int mt = 0; mt < MT; mt++)
#pragma unroll
                for (int rr = 0; rr < 2; rr++) {
                    pel[mt][rr]  += __shfl_xor_sync(0xffffffffu, pel[mt][rr], off);
                    per_[mt][rr] += __shfl_xor_sync(0xffffffffu, per_[mt][rr], off);
                }
        }
        __syncthreads();
        if (tig == 0) {
#pragma unroll
            for (int mt = 0; mt < MT; mt++)
#pragma unroll
                for (int rr = 0; rr < 2; rr++) {
                    int lrow = wm * RPW + mt * 16 + group + rr * 8;
                    sf[wn * (TBM * 2) + lrow * 2]     = pel[mt][rr];
                    sf[wn * (TBM * 2) + lrow * 2 + 1] = per_[mt][rr];
                }
        }
        __syncthreads();
        if (t < TBM) {
            int grow = bm + t;
            if (grow < M) {
                el[grow] = sf[t * 2]     + sf[TBM * 2 + t * 2];
                er[grow] = sf[t * 2 + 1] + sf[TBM * 2 + t * 2 + 1];
            }
        }
    }
}

// ---------------- BatchNorm ----------------
__global__ void bn_stats(const float* __restrict__ x, double* sum, double* sq, int M) {
    const int col = threadIdx.x & 63;
    const int rlane = threadIdx.x >> 6;
    double s = 0, q = 0;
    for (int r = blockIdx.x * 4 + rlane; r < M; r += gridDim.x * 4) {
        double v = x[(size_t)r * HF + col];
        s += v; q += v * v;
    }
    __shared__ double sh[2][256];
    sh[0][threadIdx.x] = s; sh[1][threadIdx.x] = q;
    __syncthreads();
    if (rlane == 0) {
#pragma unroll
        for (int i = 1; i < 4; i++) { s += sh[0][i * 64 + col]; q += sh[1][i * 64 + col]; }
        atomicAdd(&sum[col], s);
        atomicAdd(&sq[col], q);
    }
}

__global__ void bn_apply_bf(const float* __restrict__ x, const double* __restrict__ sum,
                            const double* __restrict__ sq, const float* __restrict__ g,
                            const float* __restrict__ b,
                            __nv_bfloat16* __restrict__ hi, __nv_bfloat16* __restrict__ lo,
                            int M) {
    int idx = blockIdx.x * blockDim.x + threadIdx.x;
    if (idx >= M * HF) return;
    int c = idx & 63;
    double mu = sum[c] / M;
    double var = sq[c] / M - mu * mu;
    float inv = rsqrtf((float)var + 1e-5f);
    float y = ((float)(x[idx] - mu)) * inv * g[c] + b[c];
    y = y > 0.f ? y : 0.01f * y;
    split_wr(y, &hi[idx], &lo[idx]);
}

// ---------------- fused GAT: ONE-PASS online softmax, 4-edge batches ----------------
template <int H, bool WB, bool FC>
__global__ void gat_agg(const __half* __restrict__ fh, const float* __restrict__ el,
                        const float* __restrict__ er, const int* __restrict__ rowptr,
                        const int* __restrict__ srcp, const float* __restrict__ bias,
                        const float* __restrict__ fcW, const float* __restrict__ fcb,
                        float* __restrict__ out,
                        __nv_bfloat16* __restrict__ ohi, __nv_bfloat16* __restrict__ olo) {
    constexpr int HD  = H * 64;
    constexpr int CPL = HD / 32;
    int node = (blockIdx.x * blockDim.x + threadIdx.x) >> 5;
    if (node >= NN) return;
    int lane = threadIdx.x & 31;
    int h  = (H == 4) ? (lane >> 3) : 0;
    int c0 = lane * CPL;
    int s0 = rowptr[node], s1 = rowptr[node + 1];
    float outv[CPL];
    if (s0 == s1) {
#pragma unroll
        for (int i = 0; i < CPL; i++) {
            float y = bias[c0 + i];
            outv[i] = y > 0.f ? y : 0.01f * y;
        }
    } else {
        float ern = er[node * H + h];
        int sfb = __ldg(&srcp[s0]);
        float m = -3.4e38f;
        float den = 0.f;
        float acc[CPL] = {};
        for (int e = s0; e < s1; e += 4) {
            int sx[4];
#pragma unroll
            for (int j = 0; j < 4; j++)
                sx[j] = (e + j) < s1 ? __ldg(&srcp[e + j]) : sfb;
            float vv[4];
#pragma unroll
            for (int j = 0; j < 4; j++) {
                float v = __ldg(&el[sx[j] * H + h]) + ern;
                v = v > 0.f ? v : 0.2f * v;
                vv[j] = (e + j) < s1 ? v : -3.4e38f;
            }
            if constexpr (CPL == 8) {
                uint4 raw[4];
#pragma unroll
                for (int j = 0; j < 4; j++)
                    raw[j] = *(const uint4*)(fh + (size_t)sx[j] * HD + c0);
                float bmax = fmaxf(fmaxf(vv[0], vv[1]), fmaxf(vv[2], vv[3]));
                if (bmax > m) {
                    float sc = __expf(m - bmax);
                    den *= sc;
#pragma unroll
                    for (int i = 0; i < CPL; i++) acc[i] *= sc;
                    m = bmax;
                }
#pragma unroll
                for (int j = 0; j < 4; j++) {
                    float ex = __expf(vv[j] - m);
                    den += ex;
                    const __half2* hp = (const __half2*)&raw[j];
#pragma unroll
                    for (int q = 0; q < 4; q++) {
                        float2 mv = __half22float2(hp[q]);
                        acc[2 * q]     = fmaf(ex, mv.x, acc[2 * q]);
                        acc[2 * q + 1] = fmaf(ex, mv.y, acc[2 * q + 1]);
                    }
                }
            } else {
                uint32_t raw[4];
#pragma unroll
                for (int j = 0; j < 4; j++)
                    raw[j] = *(const uint32_t*)(fh + (size_t)sx[j] * HD + c0);
                float bmax = fmaxf(fmaxf(vv[0], vv[1]), fmaxf(vv[2], vv[3]));
                if (bmax > m) {
                    float sc = __expf(m - bmax);
                    den *= sc;
#pragma unroll
                    for (int i = 0; i < CPL; i++) acc[i] *= sc;
                    m = bmax;
                }
#pragma unroll
                for (int j = 0; j < 4; j++) {
                    float ex = __expf(vv[j] - m);
                    den += ex;
                    float2 mv = __half22float2(*(const __half2*)&raw[j]);
                    acc[0] = fmaf(ex, mv.x, acc[0]);
                    acc[1] = fmaf(ex, mv.y, acc[1]);
                }
            }
        }
        float inv = 1.f / den;
#pragma unroll
        for (int i = 0; i < CPL; i++) {
            float y = acc[i] * inv + bias[c0 + i];
            outv[i] = y > 0.f ? y : 0.01f * y;
        }
    }
    if constexpr (FC) {
        float p0 = outv[0] * fcW[c0 * 2]     + outv[1] * fcW[(c0 + 1) * 2];
        float p1 = outv[0] * fcW[c0 * 2 + 1] + outv[1] * fcW[(c0 + 1) * 2 + 1];
#pragma unroll
        for (int off = 16; off; off >>= 1) {
            p0 += __shfl_xor_sync(0xffffffffu, p0, off);
            p1 += __shfl_xor_sync(0xffffffffu, p1, off);
        }
        if (lane == 0) {
            out[node * 2]     = p0 + fcb[0];
            out[node * 2 + 1] = p1 + fcb[1];
        }
    } else if constexpr (WB) {
        __nv_bfloat162 hp[CPL / 2], lp[CPL / 2];
#pragma unroll
        for (int j = 0; j < CPL / 2; j++) {
            float x = outv[2 * j], y = outv[2 * j + 1];
            __nv_bfloat162 h2 = __floats2bfloat162_rn(x, y);
            hp[j] = h2;
            lp[j] = __floats2bfloat162_rn(x - __bfloat162float(h2.x),
                                          y - __bfloat162float(h2.y));
        }
        size_t off = (size_t)node * HD + c0;
        *(uint4*)&ohi[off] = *(uint4*)hp;
        *(uint4*)&olo[off] = *(uint4*)lp;
    }
}

// ---------------- host ----------------
static inline int cdiv(long a, long b) { return (int)((a + b - 1) / b); }

extern "C" void kernel_launch(void* const* d_in, const int* in_sizes, int n_in,
                              void* d_out, int out_size) {
    const float* feat    = (const float*)d_in[0];
    const int*   src     = (const int*)  d_in[1];
    const int*   dst     = (const int*)  d_in[2];
    const float* enc1_W  = (const float*)d_in[3];
    const float* bn1_g   = (const float*)d_in[5];
    const float* bn1_b   = (const float*)d_in[6];
    const float* enc2_W  = (const float*)d_in[7];
    const float* bn2_g   = (const float*)d_in[9];
    const float* bn2_b   = (const float*)d_in[10];
    const float* gat0_W  = (const float*)d_in[11];
    const float* gat0_al = (const float*)d_in[12];
    const float* gat0_ar = (const float*)d_in[13];
    const float* gat0_b  = (const float*)d_in[14];
    const float* gatm_W  = (const float*)d_in[15];
    const float* gatm_al = (const float*)d_in[16];
    const float* gatm_ar = (const float*)d_in[17];
    const float* gatm_b  = (const float*)d_in[18];
    const float* gat4_W  = (const float*)d_in[19];
    const float* gat4_al = (const float*)d_in[20];
    const float* gat4_ar = (const float*)d_in[21];
    const float* gat4_b  = (const float*)d_in[22];
    const float* fc_W    = (const float*)d_in[23];
    const float* fc_b    = (const float*)d_in[24];
    float* out = (float*)d_out;

    float *tmp, *el, *er;
    __half* fh;
    __nv_bfloat16 *ahi, *alo, *whi, *wlo;
    double *bnstat;
    int *rowptr, *cnt, *cnt2, *srcp;
    cudaGetSymbolAddress((void**)&fh,     g_fh);
    cudaGetSymbolAddress((void**)&tmp,    g_t);
    cudaGetSymbolAddress((void**)&ahi,    g_ahi);
    cudaGetSymbolAddress((void**)&alo,    g_alo);
    cudaGetSymbolAddress((void**)&whi,    g_whi);
    cudaGetSymbolAddress((void**)&wlo,    g_wlo);
    cudaGetSymbolAddress((void**)&el,     g_el);
    cudaGetSymbolAddress((void**)&er,     g_er);
    cudaGetSymbolAddress((void**)&bnstat, g_bnstat);
    cudaGetSymbolAddress((void**)&rowptr, g_rowptr);
    cudaGetSymbolAddress((void**)&cnt,    g_cnt);
    cudaGetSymbolAddress((void**)&cnt2,   g_cnt2);
    cudaGetSymbolAddress((void**)&srcp,   g_srcp);

    const int SM64_128 = (4 * 64 * 40 + 4 * 32 * (128 + 8)) * 2;  // 55296
    const int SM64     = (4 * 64 * 40 + 4 * 32 * (64 + 8)) * 2;   // 38912
    cudaFuncSetAttribute((const void*)gemm3<64, 128, 4, true, false>,
                         cudaFuncAttributeMaxDynamicSharedMemorySize, SM64_128);
    cudaFuncSetAttribute((const void*)gemm3<64, 64, 0, false, true>,
                         cudaFuncAttributeMaxDynamicSharedMemorySize, SM64);
    cudaFuncSetAttribute((const void*)gemm3<64, 64, 1, true, false>,
                         cudaFuncAttributeMaxDynamicSharedMemorySize, SM64);

    const int MB64 = cdiv(NN, 64);   // 313
    const int WARP_BLOCKS = cdiv((long)NN * 32, 256);

    // ---- prologue ----
    split_feat_zero<<<cdiv((long)NN * 64, 256), 256>>>(feat, ahi, alo, cnt, cnt2, bnstat);
    splitW_all<<<cdiv(W_TOTAL, 256), 256>>>(enc1_W, enc2_W, gat0_W, gatm_W, gat4_W, whi, wlo);
    hist_k<<<cdiv(EE, 256), 256>>>(dst, cnt);
    gemm3<64, 64, 0, false, true><<<dim3(1, MB64), 256, SM64>>>(
        ahi, alo, whi + W_ENC1, wlo + W_ENC1, tmp, nullptr, NN, HF, 64,
        nullptr, nullptr, nullptr, nullptr);  // launch idx 3 (ncu slot)
    scan_k<<<1, 1024>>>(cnt, rowptr);
    scatter_k<<<cdiv(EE, 256), 256>>>(src, dst, rowptr, cnt2, srcp);

    // ---- encoder (biases cancel inside training-mode BN) ----
    bn_stats<<<120, 256>>>(tmp, bnstat, bnstat + HF, NN);
    bn_apply_bf<<<cdiv((long)NN * HF, 256), 256>>>(tmp, bnstat, bnstat + HF,
                                                   bn1_g, bn1_b, ahi, alo, NN);
    gemm3<64, 64, 0, false, true><<<dim3(1, MB64), 256, SM64>>>(
        ahi, alo, whi + W_ENC2, wlo + W_ENC2, tmp, nullptr, NN, HF, 64,
        nullptr, nullptr, nullptr, nullptr);
    bn_stats<<<120, 256>>>(tmp, bnstat + 2 * HF, bnstat + 3 * HF, NN);
    bn_apply_bf<<<cdiv((long)NN * HF, 256), 256>>>(tmp, bnstat + 2 * HF, bnstat + 3 * HF,
                                                   bn2_g, bn2_b, ahi, alo, NN);

    // ---- GAT stack (all GEMMs TBM=64, 3 CTAs/SM) ----
    gemm3<64, 128, 4, true, false><<<dim3(2, MB64), 256, SM64_128>>>(
        ahi, alo, whi + W_GAT0, wlo + W_GAT0, nullptr, fh, NN, HDMAX, 64,
        gat0_al, gat0_ar, el, er);
    gat_agg<4, true, false><<<WARP_BLOCKS, 256>>>(fh, el, er, rowptr, srcp, gat0_b,
                                                  nullptr, nullptr, nullptr, ahi, alo);
    for (int i = 0; i < 3; i++) {
        gemm3<64, 128, 4, true, false><<<dim3(2, MB64), 256, SM64_128>>>(
            ahi, alo, whi + W_GATM + (size_t)i * HDMAX * HDMAX,
            wlo + W_GATM + (size_t)i * HDMAX * HDMAX, nullptr, fh, NN, HDMAX, HDMAX,
            gatm_al + i * NHEADS * HF, gatm_ar + i * NHEADS * HF, el, er);
        gat_agg<4, true, false><<<WARP_BLOCKS, 256>>>(fh, el, er, rowptr, srcp,
                                                      gatm_b + i * HDMAX,
                                                      nullptr, nullptr, nullptr, ahi, alo);
    }
    gemm3<64, 64, 1, true, false><<<dim3(1, MB64), 256, SM64>>>(
        ahi, alo, whi + W_GAT4, wlo + W_GAT4, nullptr, fh, NN, HF, HDMAX,
        gat4_al, gat4_ar, el, er);
    gat_agg<1, false, true><<<WARP_BLOCKS, 256>>>(fh, el, er, rowptr, srcp, gat4_b,
                                                  fc_W, fc_b, out, nullptr, nullptr);
}

// round 16
// speedup vs baseline: 1.0690x; 1.0066x over previous
#include <cuda_runtime.h>
#include <cuda_bf16.h>
#include <cuda_fp16.h>
#include <cstdint>

#define NN 20000
#define EE 320000
#define FIN 33
#define HF 64
#define NHEADS 4
#define HDMAX 256

// weight arena segment offsets (bf16 elems)
#define W_ENC1 0
#define W_ENC2 4096
#define W_GAT0 8192
#define W_GATM 24576
#define W_GAT4 221184
#define W_TOTAL 237568

// ---------------- scratch ----------------
__device__ __half         g_fh[NN * HDMAX];
__device__ float          g_t[NN * HF];
__device__ __nv_bfloat16  g_ahi[NN * HDMAX];
__device__ __nv_bfloat16  g_alo[NN * HDMAX];
__device__ __nv_bfloat16  g_whi[W_TOTAL];
__device__ __nv_bfloat16  g_wlo[W_TOTAL];
__device__ float  g_el[NN * NHEADS];
__device__ float  g_er[NN * NHEADS];
__device__ double g_bnstat[4 * HF];
__device__ int g_rowptr[NN + 1];
__device__ int g_cnt[NN];
__device__ int g_cnt2[NN];
__device__ int g_srcp[EE];

__device__ __forceinline__ void split_wr(float v, __nv_bfloat16* hi, __nv_bfloat16* lo) {
    __nv_bfloat16 h = __float2bfloat16_rn(v);
    *hi = h;
    *lo = __float2bfloat16_rn(v - __bfloat162float(h));
}

// ---------------- prologue ----------------
__global__ void split_feat_zero(const float* __restrict__ x,
                                __nv_bfloat16* __restrict__ hi,
                                __nv_bfloat16* __restrict__ lo,
                                int* __restrict__ cnt, int* __restrict__ cnt2,
                                double* __restrict__ bs) {
    int idx = blockIdx.x * blockDim.x + threadIdx.x;
    if (idx < NN) { cnt[idx] = 0; cnt2[idx] = 0; }
    if (idx < 4 * HF) bs[idx] = 0.0;
    if (idx >= NN * 64) return;
    int row = idx >> 6, col = idx & 63;
    float v = (col < FIN) ? x[row * FIN + col] : 0.f;
    split_wr(v, &hi[idx], &lo[idx]);
}

// split ALL weights + fused dst histogram (cnt zeroed by preceding kernel; in-stream
// serialization guarantees ordering). Grid sized for max(W_TOTAL, EE).
__global__ void splitW_hist(const float* __restrict__ enc1, const float* __restrict__ enc2,
                            const float* __restrict__ gat0, const float* __restrict__ gatm,
                            const float* __restrict__ gat4,
                            __nv_bfloat16* __restrict__ hi, __nv_bfloat16* __restrict__ lo,
                            const int* __restrict__ dst, int* __restrict__ cnt) {
    int idx = blockIdx.x * blockDim.x + threadIdx.x;
    if (idx < EE) atomicAdd(&cnt[dst[idx]], 1);
    if (idx >= W_TOTAL) return;
    float v;
    if (idx < W_ENC2) {
        int row = idx >> 6, col = idx & 63;
        v = (row < FIN) ? enc1[row * 64 + col] : 0.f;
    } else if (idx < W_GAT0) {
        v = enc2[idx - W_ENC2];
    } else if (idx < W_GATM) {
        v = gat0[idx - W_GAT0];
    } else if (idx < W_GAT4) {
        v = gatm[idx - W_GATM];
    } else {
        v = gat4[idx - W_GAT4];
    }
    split_wr(v, &hi[idx], &lo[idx]);
}

// ---------------- CSR build ----------------
__global__ void scan_k(const int* __restrict__ cnt, int* __restrict__ rowptr) {
    __shared__ int sh[1024];
    const int t = threadIdx.x;
    const int C = (NN + 1023) / 1024;
    int base = t * C;
    int local[C];
    int s = 0;
#pragma unroll
    for (int i = 0; i < C; i++) {
        int v = (base + i < NN) ? cnt[base + i] : 0;
        local[i] = s; s += v;
    }
    sh[t] = s;
    __syncthreads();
    for (int off = 1; off < 1024; off <<= 1) {
        int v = (t >= off) ? sh[t - off] : 0;
        __syncthreads();
        sh[t] += v;
        __syncthreads();
    }
    int pre = (t > 0) ? sh[t - 1] : 0;
#pragma unroll
    for (int i = 0; i < C; i++)
        if (base + i < NN) rowptr[base + i] = pre + local[i];
    if (t == 1023) rowptr[NN] = sh[1023];
}

__global__ void scatter_k(const int* __restrict__ src, const int* __restrict__ dst,
                          const int* __restrict__ rowptr, int* __restrict__ cnt2,
                          int* __restrict__ srcp) {
    int e = blockIdx.x * blockDim.x + threadIdx.x;
    if (e >= EE) return;
    int d = dst[e];
    int pos = rowptr[d] + atomicAdd(&cnt2[d], 1);
    srcp[pos] = src[e];
}

// ---------------- bf16 3-term GEMM + fused el/er epilogues ----------------
__device__ __forceinline__ void mma16(float* c, const uint32_t* a, const uint32_t* b) {
    asm volatile(
        "mma.sync.aligned.m16n8k16.row.col.f32.bf16.bf16.f32 "
        "{%0,%1,%2,%3}, {%4,%5,%6,%7}, {%8,%9}, {%0,%1,%2,%3};"
        : "+f"(c[0]), "+f"(c[1]), "+f"(c[2]), "+f"(c[3])
        : "r"(a[0]), "r"(a[1]), "r"(a[2]), "r"(a[3]), "r"(b[0]), "r"(b[1]));
}

__device__ __forceinline__ void ldmx4(uint32_t* r, uint32_t addr) {
    asm volatile("ldmatrix.sync.aligned.m8n8.x4.shared.b16 {%0,%1,%2,%3}, [%4];"
                 : "=r"(r[0]), "=r"(r[1]), "=r"(r[2]), "=r"(r[3]) : "r"(addr));
}

__device__ __forceinline__ void ldmx4t(uint32_t* r, uint32_t addr) {
    asm volatile("ldmatrix.sync.aligned.m8n8.x4.trans.shared.b16 {%0,%1,%2,%3}, [%4];"
                 : "=r"(r[0]), "=r"(r[1]), "=r"(r[2]), "=r"(r[3]) : "r"(addr));
}

__device__ __forceinline__ void cpasync16(uint32_t dst, const void* src, int sz) {
    asm volatile("cp.async.cg.shared.global [%0], [%1], 16, %2;"
                 :: "r"(dst), "l"(src), "r"(sz));
}

// TBM: block M tile. ELRM: 0 none; 4 per-head fused el/er (BN=128); 1 single-head (BN=64).
// WF16: write fp16 messages. WF32: write fp32 C.
template <int TBM, int BN, int ELRM, bool WF16, bool WF32>
__global__ void __launch_bounds__(256, TBM == 64 ? 3 : 2)
gemm3(const __nv_bfloat16* __restrict__ Ahi, const __nv_bfloat16* __restrict__ Alo,
      const __nv_bfloat16* __restrict__ Bhi, const __nv_bfloat16* __restrict__ Blo,
      float* __restrict__ C, __half* __restrict__ Fh, int M, int N, int K,
      const float* __restrict__ al, const float* __restrict__ ar,
      float* __restrict__ el, float* __restrict__ er) {
    constexpr int BK = 32;
    constexpr int MT = TBM / 64;
    constexpr int RPW = TBM / 4;
    constexpr int ASTR = 40;
    constexpr int BSTR = BN + 8;
    constexpr int WN = BN / 2, NT = WN / 8;
    constexpr int ATILE = TBM * ASTR;
    constexpr int BTILE = BK * BSTR;
    extern __shared__ __nv_bfloat16 smem[];
    __nv_bfloat16* sA = smem;
    __nv_bfloat16* sB = smem + 4 * ATILE;
    const uint32_t sAu = (uint32_t)__cvta_generic_to_shared(sA);
    const uint32_t sBu = (uint32_t)__cvta_generic_to_shared(sB);

    const int t = threadIdx.x;
    const int warp = t >> 5, lane = t & 31;
    const int wm = warp >> 1, wn = warp & 1;
    const int group = lane >> 2, tig = lane & 3;
    const int bm = blockIdx.y * TBM, bn = blockIdx.x * BN;

    float acc[MT][NT][4];
#pragma unroll
    for (int i = 0; i < MT; i++)
#pragma unroll
        for (int j = 0; j < NT; j++)
#pragma unroll
            for (int q = 0; q < 4; q++) acc[i][j][q] = 0.f;

    auto stage_load = [&](int kt, int stg) {
        const int k0 = kt * BK;
#pragma unroll
        for (int p = 0; p < 2; p++) {
            const __nv_bfloat16* Ag = p ? Alo : Ahi;
#pragma unroll
            for (int i = 0; i < MT; i++) {
                int c = t + i * 256;
                int row = c >> 2, colb = (c & 3) * 8;
                uint32_t dst = sAu + (uint32_t)(((stg * 2 + p) * ATILE + row * ASTR + colb) * 2);
                int grow = bm + row;
                const __nv_bfloat16* src = Ag + (size_t)(grow < M ? grow : 0) * K + k0 + colb;
                cpasync16(dst, src, grow < M ? 16 : 0);
            }
        }
        constexpr int CPROW = BN / 8;
        constexpr int NB = (BK * CPROW) / 256;
#pragma unroll
        for (int p = 0; p < 2; p++) {
            const __nv_bfloat16* Bg = p ? Blo : Bhi;
#pragma unroll
            for (int i = 0; i < NB; i++) {
                int c = t + i * 256;
                int row = c / CPROW, colb = (c % CPROW) * 8;
                uint32_t dst = sBu + (uint32_t)(((stg * 2 + p) * BTILE + row * BSTR + colb) * 2);
                cpasync16(dst, Bg + (size_t)(k0 + row) * N + bn + colb, 16);
            }
        }
    };

    auto compute = [&](int stg) {
#pragma unroll
        for (int ks = 0; ks < 2; ks++) {
            const int k = ks * 16;
            uint32_t Ah[MT][4], Al[MT][4];
#pragma unroll
            for (int mt = 0; mt < MT; mt++) {
                int row = wm * RPW + mt * 16 + (lane & 15);
                int col = k + 8 * (lane >> 4);
                ldmx4(Ah[mt], sAu + (uint32_t)(((stg * 2 + 0) * ATILE + row * ASTR + col) * 2));
                ldmx4(Al[mt], sAu + (uint32_t)(((stg * 2 + 1) * ATILE + row * ASTR + col) * 2));
            }
            const int brow = k + (lane & 7) + 8 * ((lane >> 3) & 1);
#pragma unroll
            for (int ntp = 0; ntp < NT / 2; ntp++) {
                int col = wn * WN + ntp * 16 + 8 * (lane >> 4);
                uint32_t Bh[4], Bl[4];
                ldmx4t(Bh, sBu + (uint32_t)(((stg * 2 + 0) * BTILE + brow * BSTR + col) * 2));
                ldmx4t(Bl, sBu + (uint32_t)(((stg * 2 + 1) * BTILE + brow * BSTR + col) * 2));
#pragma unroll
                for (int hf = 0; hf < 2; hf++) {
                    uint32_t bh2[2] = {Bh[2 * hf], Bh[2 * hf + 1]};
                    uint32_t bl2[2] = {Bl[2 * hf], Bl[2 * hf + 1]};
#pragma unroll
                    for (int mt = 0; mt < MT; mt++) {
                        float* a_ = acc[mt][2 * ntp + hf];
                        mma16(a_, Ah[mt], bh2);
                        mma16(a_, Ah[mt], bl2);
                        mma16(a_, Al[mt], bh2);
                    }
                }
            }
        }
    };

    const int KT = K / BK;
    stage_load(0, 0);
    asm volatile("cp.async.commit_group;");
    for (int kt = 0; kt < KT; kt++) {
        if (kt + 1 < KT) {
            stage_load(kt + 1, (kt + 1) & 1);
            asm volatile("cp.async.commit_group;");
            asm volatile("cp.async.wait_group 1;");
        } else {
            asm volatile("cp.async.wait_group 0;");
        }
        __syncthreads();
        compute(kt & 1);
        __syncthreads();
    }

    // epilogue: stores
#pragma unroll
    for (int mt = 0; mt < MT; mt++) {
        int r0 = bm + wm * RPW + mt * 16 + group;
        int r1 = r0 + 8;
#pragma unroll
        for (int nt = 0; nt < NT; nt++) {
            int c = bn + wn * WN + nt * 8 + tig * 2;
            if constexpr (WF32) {
                if (r0 < M) *(float2*)&C[(size_t)r0 * N + c] = make_float2(acc[mt][nt][0], acc[mt][nt][1]);
                if (r1 < M) *(float2*)&C[(size_t)r1 * N + c] = make_float2(acc[mt][nt][2], acc[mt][nt][3]);
            }
            if constexpr (WF16) {
                if (r0 < M) *(__half2*)&Fh[(size_t)r0 * N + c] = __floats2half2_rn(acc[mt][nt][0], acc[mt][nt][1]);
                if (r1 < M) *(__half2*)&Fh[(size_t)r1 * N + c] = __floats2half2_rn(acc[mt][nt][2], acc[mt][nt][3]);
            }
        }
    }

    if constexpr (ELRM == 4) {
        const int head = blockIdx.x * 2 + wn;
        float pel[MT][2] = {}, per_[MT][2] = {};
#pragma unroll
        for (int nt = 0; nt < NT; nt++) {
            int d = nt * 8 + tig * 2;
            float a0 = al[head * 64 + d], a1 = al[head * 64 + d + 1];
            float b0 = ar[head * 64 + d], b1 = ar[head * 64 + d + 1];
#pragma unroll
            for (int mt = 0; mt < MT; mt++) {
                pel[mt][0]  += acc[mt][nt][0] * a0 + acc[mt][nt][1] * a1;
                pel[mt][1]  += acc[mt][nt][2] * a0 + acc[mt][nt][3] * a1;
                per_[mt][0] += acc[mt][nt][0] * b0 + acc[mt][nt][1] * b1;
                per_[mt][1] += acc[mt][nt][2] * b0 + acc[mt][nt][3] * b1;
            }
        }
#pragma unroll
        for (int off = 1; off <= 2; off <<= 1) {
#pragma unroll
            for (int mt = 0; mt < MT; mt++)
#pragma unroll
                for (int rr = 0; rr < 2; rr++) {
                    pel[mt][rr]  += __shfl_xor_sync(0xffffffffu, pel[mt][rr], off);
                    per_[mt][rr] += __shfl_xor_sync(0xffffffffu, per_[mt][rr], off);
                }
        }
        if (tig == 0) {
#pragma unroll
            for (int mt = 0; mt < MT; mt++) {
                int r0 = bm + wm * RPW + mt * 16 + group;
                if (r0 < M)     { el[r0 * 4 + head] = pel[mt][0]; er[r0 * 4 + head] = per_[mt][0]; }
                if (r0 + 8 < M) { el[(r0 + 8) * 4 + head] = pel[mt][1]; er[(r0 + 8) * 4 + head] = per_[mt][1]; }
            }
        }
    }

    if constexpr (ELRM == 1) {
        float* sf = (float*)smem;
        float pel[MT][2] = {}, per_[MT][2] = {};
#pragma unroll
        for (int nt = 0; nt < NT; nt++) {
            int c = wn * WN + nt * 8 + tig * 2;
            float a0 = al[c], a1 = al[c + 1];
            float b0 = ar[c], b1 = ar[c + 1];
#pragma unroll
            for (int mt = 0; mt < MT; mt++) {
                pel[mt][0]  += acc[mt][nt][0] * a0 + acc[mt][nt][1] * a1;
                pel[mt][1]  += acc[mt][nt][2] * a0 + acc[mt][nt][3] * a1;
                per_[mt][0] += acc[mt][nt][0] * b0 + acc[mt][nt][1] * b1;
                per_[mt][1] += acc[mt][nt][2] * b0 + acc[mt][nt][3] * b1;
            }
        }
#pragma unroll
        for (int off = 1; off <= 2; off <<= 1) {
#pragma unroll
            for (int mt = 0; mt < MT; mt++)
#pragma unroll
                for (int rr = 0; rr < 2; rr++) {
                    pel[mt][rr]  += __shfl_xor_sync(0xffffffffu, pel[mt][rr], off);
                    per_[mt][rr] += __shfl_xor_sync(0xffffffffu, per_[mt][rr], off);
                }
        }
        __syncthreads();
        if (tig == 0) {
#pragma unroll
            for (int mt = 0; mt < MT; mt++)
#pragma unroll
                for (int rr = 0; rr < 2; rr++) {
                    int lrow = wm * RPW + mt * 16 + group + rr * 8;
                    sf[wn * (TBM * 2) + lrow * 2]     = pel[mt][rr];
                    sf[wn * (TBM * 2) + lrow * 2 + 1] = per_[mt][rr];
                }
        }
        __syncthreads();
        if (t < TBM) {
            int grow = bm + t;
            if (grow < M) {
                el[grow] = sf[t * 2]     + sf[TBM * 2 + t * 2];
                er[grow] = sf[t * 2 + 1] + sf[TBM * 2 + t * 2 + 1];
            }
        }
    }
}

// ---------------- BatchNorm ----------------
__global__ void bn_stats(const float* __restrict__ x, double* sum, double* sq, int M) {
    const int col = threadIdx.x & 63;
    const int rlane = threadIdx.x >> 6;
    double s = 0, q = 0;
    for (int r = blockIdx.x * 4 + rlane; r < M; r += gridDim.x * 4) {
        double v = x[(size_t)r * HF + col];
        s += v; q += v * v;
    }
    __shared__ double sh[2][256];
    sh[0][threadIdx.x] = s; sh[1][threadIdx.x] = q;
    __syncthreads();
    if (rlane == 0) {
#pragma unroll
        for (int i = 1; i < 4; i++) { s += sh[0][i * 64 + col]; q += sh[1][i * 64 + col]; }
        atomicAdd(&sum[col], s);
        atomicAdd(&sq[col], q);
    }
}

__global__ void bn_apply_bf(const float* __restrict__ x, const double* __restrict__ sum,
                            const double* __restrict__ sq, const float* __restrict__ g,
                            const float* __restrict__ b,
                            __nv_bfloat16* __restrict__ hi, __nv_bfloat16* __restrict__ lo,
                            int M) {
    int idx = blockIdx.x * blockDim.x + threadIdx.x;
    if (idx >= M * HF) return;
    int c = idx & 63;
    double mu = sum[c] / M;
    double var = sq[c] / M - mu * mu;
    float inv = rsqrtf((float)var + 1e-5f);
    float y = ((float)(x[idx] - mu)) * inv * g[c] + b[c];
    y = y > 0.f ? y : 0.01f * y;
    split_wr(y, &hi[idx], &lo[idx]);
}

// ---------------- fused GAT: ONE-PASS online softmax, 4-edge batches ----------------
template <int H, bool WB, bool FC>
__global__ void gat_agg(const __half* __restrict__ fh, const float* __restrict__ el,
                        const float* __restrict__ er, const int* __restrict__ rowptr,
                        const int* __restrict__ srcp, const float* __restrict__ bias,
                        const float* __restrict__ fcW, const float* __restrict__ fcb,
                        float* __restrict__ out,
                        __nv_bfloat16* __restrict__ ohi, __nv_bfloat16* __restrict__ olo) {
    constexpr int HD  = H * 64;
    constexpr int CPL = HD / 32;
    int node = (blockIdx.x * blockDim.x + threadIdx.x) >> 5;
    if (node >= NN) return;
    int lane = threadIdx.x & 31;
    int h  = (H == 4) ? (lane >> 3) : 0;
    int c0 = lane * CPL;
    int s0 = rowptr[node], s1 = rowptr[node + 1];
    float outv[CPL];
    if (s0 == s1) {
#pragma unroll
        for (int i = 0; i < CPL; i++) {
            float y = bias[c0 + i];
            outv[i] = y > 0.f ? y : 0.01f * y;
        }
    } else {
        float ern = er[node * H + h];
        int sfb = __ldg(&srcp[s0]);
        float m = -3.4e38f;
        float den = 0.f;
        float acc[CPL] = {};
        for (int e = s0; e < s1; e += 4) {
            int sx[4];
#pragma unroll
            for (int j = 0; j < 4; j++)
                sx[j] = (e + j) < s1 ? __ldg(&srcp[e + j]) : sfb;
            float vv[4];
#pragma unroll
            for (int j = 0; j < 4; j++) {
                float v = __ldg(&el[sx[j] * H + h]) + ern;
                v = v > 0.f ? v : 0.2f * v;
                vv[j] = (e + j) < s1 ? v : -3.4e38f;
            }
            if constexpr (CPL == 8) {
                uint4 raw[4];
#pragma unroll
                for (int j = 0; j < 4; j++)
                    raw[j] = *(const uint4*)(fh + (size_t)sx[j] * HD + c0);
                float bmax = fmaxf(fmaxf(vv[0], vv[1]), fmaxf(vv[2], vv[3]));
                if (bmax > m) {
                    float sc = __expf(m - bmax);
                    den *= sc;
#pragma unroll
                    for (int i = 0; i < CPL; i++) acc[i] *= sc;
                    m = bmax;
                }
#pragma unroll
                for (int j = 0; j < 4; j++) {
                    float ex = __expf(vv[j] - m);
                    den += ex;
                    const __half2* hp = (const __half2*)&raw[j];
#pragma unroll
                    for (int q = 0; q < 4; q++) {
                        float2 mv = __half22float2(hp[q]);
                        acc[2 * q]     = fmaf(ex, mv.x, acc[2 * q]);
                        acc[2 * q + 1] = fmaf(ex, mv.y, acc[2 * q + 1]);
                    }
                }
            } else {
                uint32_t raw[4];
#pragma unroll
                for (int j = 0; j < 4; j++)
                    raw[j] = *(const uint32_t*)(fh + (size_t)sx[j] * HD + c0);
                float bmax = fmaxf(fmaxf(vv[0], vv[1]), fmaxf(vv[2], vv[3]));
                if (bmax > m) {
                    float sc = __expf(m - bmax);
                    den *= sc;
#pragma unroll
                    for (int i = 0; i < CPL; i++) acc[i] *= sc;
                    m = bmax;
                }
#pragma unroll
                for (int j = 0; j < 4; j++) {
                    float ex = __expf(vv[j] - m);
                    den += ex;
                    float2 mv = __half22float2(*(const __half2*)&raw[j]);
                    acc[0] = fmaf(ex, mv.x, acc[0]);
                    acc[1] = fmaf(ex, mv.y, acc[1]);
                }
            }
        }
        float inv = 1.f / den;
#pragma unroll
        for (int i = 0; i < CPL; i++) {
            float y = acc[i] * inv + bias[c0 + i];
            outv[i] = y > 0.f ? y : 0.01f * y;
        }
    }
    if constexpr (FC) {
        float p0 = outv[0] * fcW[c0 * 2]     + outv[1] * fcW[(c0 + 1) * 2];
        float p1 = outv[0] * fcW[c0 * 2 + 1] + outv[1] * fcW[(c0 + 1) * 2 + 1];
#pragma unroll
        for (int off = 16; off; off >>= 1) {
            p0 += __shfl_xor_sync(0xffffffffu, p0, off);
            p1 += __shfl_xor_sync(0xffffffffu, p1, off);
        }
        if (lane == 0) {
            out[node * 2]     = p0 + fcb[0];
            out[node * 2 + 1] = p1 + fcb[1];
        }
    } else if constexpr (WB) {
        __nv_bfloat162 hp[CPL / 2], lp[CPL / 2];
#pragma unroll
        for (int j = 0; j < CPL / 2; j++) {
            float x = outv[2 * j], y = outv[2 * j + 1];
            __nv_bfloat162 h2 = __floats2bfloat162_rn(x, y);
            hp[j] = h2;
            lp[j] = __floats2bfloat162_rn(x - __bfloat162float(h2.x),
                                          y - __bfloat162float(h2.y));
        }
        size_t off = (size_t)node * HD + c0;
        *(uint4*)&ohi[off] = *(uint4*)hp;
        *(uint4*)&olo[off] = *(uint4*)lp;
    }
}

// ---------------- host ----------------
static inline int cdiv(long a, long b) { return (int)((a + b - 1) / b); }

extern "C" void kernel_launch(void* const* d_in, const int* in_sizes, int n_in,
                              void* d_out, int out_size) {
    const float* feat    = (const float*)d_in[0];
    const int*   src     = (const int*)  d_in[1];
    const int*   dst     = (const int*)  d_in[2];
    const float* enc1_W  = (const float*)d_in[3];
    const float* bn1_g   = (const float*)d_in[5];
    const float* bn1_b   = (const float*)d_in[6];
    const float* enc2_W  = (const float*)d_in[7];
    const float* bn2_g   = (const float*)d_in[9];
    const float* bn2_b   = (const float*)d_in[10];
    const float* gat0_W  = (const float*)d_in[11];
    const float* gat0_al = (const float*)d_in[12];
    const float* gat0_ar = (const float*)d_in[13];
    const float* gat0_b  = (const float*)d_in[14];
    const float* gatm_W  = (const float*)d_in[15];
    const float* gatm_al = (const float*)d_in[16];
    const float* gatm_ar = (const float*)d_in[17];
    const float* gatm_b  = (const float*)d_in[18];
    const float* gat4_W  = (const float*)d_in[19];
    const float* gat4_al = (const float*)d_in[20];
    const float* gat4_ar = (const float*)d_in[21];
    const float* gat4_b  = (const float*)d_in[22];
    const float* fc_W    = (const float*)d_in[23];
    const float* fc_b    = (const float*)d_in[24];
    float* out = (float*)d_out;

    float *tmp, *el, *er;
    __half* fh;
    __nv_bfloat16 *ahi, *alo, *whi, *wlo;
    double *bnstat;
    int *rowptr, *cnt, *cnt2, *srcp;
    cudaGetSymbolAddress((void**)&fh,     g_fh);
    cudaGetSymbolAddress((void**)&tmp,    g_t);
    cudaGetSymbolAddress((void**)&ahi,    g_ahi);
    cudaGetSymbolAddress((void**)&alo,    g_alo);
    cudaGetSymbolAddress((void**)&whi,    g_whi);
    cudaGetSymbolAddress((void**)&wlo,    g_wlo);
    cudaGetSymbolAddress((void**)&el,     g_el);
    cudaGetSymbolAddress((void**)&er,     g_er);
    cudaGetSymbolAddress((void**)&bnstat, g_bnstat);
    cudaGetSymbolAddress((void**)&rowptr, g_rowptr);
    cudaGetSymbolAddress((void**)&cnt,    g_cnt);
    cudaGetSymbolAddress((void**)&cnt2,   g_cnt2);
    cudaGetSymbolAddress((void**)&srcp,   g_srcp);

    const int SM64_128 = (4 * 64 * 40 + 4 * 32 * (128 + 8)) * 2;  // 55296
    const int SM64     = (4 * 64 * 40 + 4 * 32 * (64 + 8)) * 2;   // 38912
    cudaFuncSetAttribute((const void*)gemm3<64, 128, 4, true, false>,
                         cudaFuncAttributeMaxDynamicSharedMemorySize, SM64_128);
    cudaFuncSetAttribute((const void*)gemm3<64, 64, 0, false, true>,
                         cudaFuncAttributeMaxDynamicSharedMemorySize, SM64);
    cudaFuncSetAttribute((const void*)gemm3<64, 64, 1, true, false>,
                         cudaFuncAttributeMaxDynamicSharedMemorySize, SM64);

    const int MB64 = cdiv(NN, 64);   // 313
    const int WARP_BLOCKS = cdiv((long)NN * 32, 256);

    // ---- prologue (hist fused into splitW; cnt zeroed by split_feat_zero,
    //      in-stream ordering guarantees it completes first) ----
    split_feat_zero<<<cdiv((long)NN * 64, 256), 256>>>(feat, ahi, alo, cnt, cnt2, bnstat);
    splitW_hist<<<cdiv(EE, 256), 256>>>(enc1_W, enc2_W, gat0_W, gatm_W, gat4_W,
                                        whi, wlo, dst, cnt);
    scan_k<<<1, 1024>>>(cnt, rowptr);
    gemm3<64, 64, 0, false, true><<<dim3(1, MB64), 256, SM64>>>(
        ahi, alo, whi + W_ENC1, wlo + W_ENC1, tmp, nullptr, NN, HF, 64,
        nullptr, nullptr, nullptr, nullptr);  // launch idx 3 (ncu slot)
    scatter_k<<<cdiv(EE, 256), 256>>>(src, dst, rowptr, cnt2, srcp);

    // ---- encoder (biases cancel inside training-mode BN) ----
    bn_stats<<<120, 256>>>(tmp, bnstat, bnstat + HF, NN);
    bn_apply_bf<<<cdiv((long)NN * HF, 256), 256>>>(tmp, bnstat, bnstat + HF,
                                                   bn1_g, bn1_b, ahi, alo, NN);
    gemm3<64, 64, 0, false, true><<<dim3(1, MB64), 256, SM64>>>(
        ahi, alo, whi + W_ENC2, wlo + W_ENC2, tmp, nullptr, NN, HF, 64,
        nullptr, nullptr, nullptr, nullptr);
    bn_stats<<<120, 256>>>(tmp, bnstat + 2 * HF, bnstat + 3 * HF, NN);
    bn_apply_bf<<<cdiv((long)NN * HF, 256), 256>>>(tmp, bnstat + 2 * HF, bnstat + 3 * HF,
                                                   bn2_g, bn2_b, ahi, alo, NN);

    // ---- GAT stack (all GEMMs TBM=64, 3 CTAs/SM) ----
    gemm3<64, 128, 4, true, false><<<dim3(2, MB64), 256, SM64_128>>>(
        ahi, alo, whi + W_GAT0, wlo + W_GAT0, nullptr, fh, NN, HDMAX, 64,
        gat0_al, gat0_ar, el, er);
    gat_agg<4, true, false><<<WARP_BLOCKS, 256>>>(fh, el, er, rowptr, srcp, gat0_b,
                                                  nullptr, nullptr, nullptr, ahi, alo);
    for (int i = 0; i < 3; i++) {
        gemm3<64, 128, 4, true, false><<<dim3(2, MB64), 256, SM64_128>>>(
            ahi, alo, whi + W_GATM + (size_t)i * HDMAX * HDMAX,
            wlo + W_GATM + (size_t)i * HDMAX * HDMAX, nullptr, fh, NN, HDMAX, HDMAX,
            gatm_al + i * NHEADS * HF, gatm_ar + i * NHEADS * HF, el, er);
        gat_agg<4, true, false><<<WARP_BLOCKS, 256>>>(fh, el, er, rowptr, srcp,
                                                      gatm_b + i * HDMAX,
                                                      nullptr, nullptr, nullptr, ahi, alo);
    }
    gemm3<64, 64, 1, true, false><<<dim3(1, MB64), 256, SM64>>>(
        ahi, alo, whi + W_GAT4, wlo + W_GAT4, nullptr, fh, NN, HF, HDMAX,
        gat4_al, gat4_ar, el, er);
    gat_agg<1, false, true><<<WARP_BLOCKS, 256>>>(fh, el, er, rowptr, srcp, gat4_b,
                                                  fc_W, fc_b, out, nullptr, nullptr);
}

// round 17
// speedup vs baseline: 1.1276x; 1.0548x over previous
#include <cuda_runtime.h>
#include <cuda_bf16.h>
#include <cuda_fp16.h>
#include <cstdint>

#define NN 20000
#define EE 320000
#define FIN 33
#define HF 64
#define NHEADS 4
#define HDMAX 256

// weight arena segment offsets (bf16 elems)
#define W_ENC1 0
#define W_ENC2 4096
#define W_GAT0 8192
#define W_GATM 24576
#define W_GAT4 221184
#define W_TOTAL 237568

// ---------------- scratch ----------------
__device__ __half         g_fh[NN * HDMAX];
__device__ float          g_t[NN * HF];
__device__ __nv_bfloat16  g_ahi[NN * HDMAX];
__device__ __nv_bfloat16  g_alo[NN * HDMAX];
__device__ __nv_bfloat16  g_whi[W_TOTAL];
__device__ __nv_bfloat16  g_wlo[W_TOTAL];
__device__ float  g_el[NN * NHEADS];
__device__ float  g_er[NN * NHEADS];
__device__ double g_bnstat[4 * HF];
__device__ int g_rowptr[NN + 1];
__device__ int g_cnt[NN];
__device__ int g_cnt2[NN];
__device__ int g_srcp[EE];

__device__ __forceinline__ void split_wr(float v, __nv_bfloat16* hi, __nv_bfloat16* lo) {
    __nv_bfloat16 h = __float2bfloat16_rn(v);
    *hi = h;
    *lo = __float2bfloat16_rn(v - __bfloat162float(h));
}

// ---------------- prologue ----------------
__global__ void split_feat_zero(const float* __restrict__ x,
                                __nv_bfloat16* __restrict__ hi,
                                __nv_bfloat16* __restrict__ lo,
                                int* __restrict__ cnt, int* __restrict__ cnt2,
                                double* __restrict__ bs) {
    int idx = blockIdx.x * blockDim.x + threadIdx.x;
    if (idx < NN) { cnt[idx] = 0; cnt2[idx] = 0; }
    if (idx < 4 * HF) bs[idx] = 0.0;
    if (idx >= NN * 64) return;
    int row = idx >> 6, col = idx & 63;
    float v = (col < FIN) ? x[row * FIN + col] : 0.f;
    split_wr(v, &hi[idx], &lo[idx]);
}

__global__ void splitW_all(const float* __restrict__ enc1, const float* __restrict__ enc2,
                           const float* __restrict__ gat0, const float* __restrict__ gatm,
                           const float* __restrict__ gat4,
                           __nv_bfloat16* __restrict__ hi, __nv_bfloat16* __restrict__ lo) {
    int idx = blockIdx.x * blockDim.x + threadIdx.x;
    if (idx >= W_TOTAL) return;
    float v;
    if (idx < W_ENC2) {
        int row = idx >> 6, col = idx & 63;
        v = (row < FIN) ? enc1[row * 64 + col] : 0.f;
    } else if (idx < W_GAT0) {
        v = enc2[idx - W_ENC2];
    } else if (idx < W_GATM) {
        v = gat0[idx - W_GAT0];
    } else if (idx < W_GAT4) {
        v = gatm[idx - W_GATM];
    } else {
        v = gat4[idx - W_GAT4];
    }
    split_wr(v, &hi[idx], &lo[idx]);
}

// ---------------- CSR build ----------------
__global__ void hist_k(const int* __restrict__ dst, int* __restrict__ cnt) {
    int e = blockIdx.x * blockDim.x + threadIdx.x;
    if (e < EE) atomicAdd(&cnt[dst[e]], 1);
}

__global__ void scan_k(const int* __restrict__ cnt, int* __restrict__ rowptr) {
    __shared__ int sh[1024];
    const int t = threadIdx.x;
    const int C = (NN + 1023) / 1024;
    int base = t * C;
    int local[C];
    int s = 0;
#pragma unroll
    for (int i = 0; i < C; i++) {
        int v = (base + i < NN) ? cnt[base + i] : 0;
        local[i] = s; s += v;
    }
    sh[t] = s;
    __syncthreads();
    for (int off = 1; off < 1024; off <<= 1) {
        int v = (t >= off) ? sh[t - off] : 0;
        __syncthreads();
        sh[t] += v;
        __syncthreads();
    }
    int pre = (t > 0) ? sh[t - 1] : 0;
#pragma unroll
    for (int i = 0; i < C; i++)
        if (base + i < NN) rowptr[base + i] = pre + local[i];
    if (t == 1023) rowptr[NN] = sh[1023];
}

__global__ void scatter_k(const int* __restrict__ src, const int* __restrict__ dst,
                          const int* __restrict__ rowptr, int* __restrict__ cnt2,
                          int* __restrict__ srcp) {
    int e = blockIdx.x * blockDim.x + threadIdx.x;
    if (e >= EE) return;
    int d = dst[e];
    int pos = rowptr[d] + atomicAdd(&cnt2[d], 1);
    srcp[pos] = src[e];
}

// ---------------- bf16 3-term GEMM + fused el/er epilogues ----------------
__device__ __forceinline__ void mma16(float* c, const uint32_t* a, const uint32_t* b) {
    asm volatile(
        "mma.sync.aligned.m16n8k16.row.col.f32.bf16.bf16.f32 "
        "{%0,%1,%2,%3}, {%4,%5,%6,%7}, {%8,%9}, {%0,%1,%2,%3};"
        : "+f"(c[0]), "+f"(c[1]), "+f"(c[2]), "+f"(c[3])
        : "r"(a[0]), "r"(a[1]), "r"(a[2]), "r"(a[3]), "r"(b[0]), "r"(b[1]));
}

__device__ __forceinline__ void ldmx4(uint32_t* r, uint32_t addr) {
    asm volatile("ldmatrix.sync.aligned.m8n8.x4.shared.b16 {%0,%1,%2,%3}, [%4];"
                 : "=r"(r[0]), "=r"(r[1]), "=r"(r[2]), "=r"(r[3]) : "r"(addr));
}

__device__ __forceinline__ void ldmx4t(uint32_t* r, uint32_t addr) {
    asm volatile("ldmatrix.sync.aligned.m8n8.x4.trans.shared.b16 {%0,%1,%2,%3}, [%4];"
                 : "=r"(r[0]), "=r"(r[1]), "=r"(r[2]), "=r"(r[3]) : "r"(addr));
}

__device__ __forceinline__ void cpasync16(uint32_t dst, const void* src, int sz) {
    asm volatile("cp.async.cg.shared.global [%0], [%1], 16, %2;"
                 :: "r"(dst), "l"(src), "r"(sz));
}

// TBM: block M tile. ELRM: 0 none; 4 per-head fused el/er (BN=128); 1 single-head (BN=64).
// WF16: write fp16 messages. WF32: write fp32 C.
template <int TBM, int BN, int ELRM, bool WF16, bool WF32>
__global__ void __launch_bounds__(256, TBM == 64 ? 3 : 2)
gemm3(const __nv_bfloat16* __restrict__ Ahi, const __nv_bfloat16* __restrict__ Alo,
      const __nv_bfloat16* __restrict__ Bhi, const __nv_bfloat16* __restrict__ Blo,
      float* __restrict__ C, __half* __restrict__ Fh, int M, int N, int K,
      const float* __restrict__ al, const float* __restrict__ ar,
      float* __restrict__ el, float* __restrict__ er) {
    constexpr int BK = 32;
    constexpr int MT = TBM / 64;
    constexpr int RPW = TBM / 4;
    constexpr int ASTR = 40;
    constexpr int BSTR = BN + 8;
    constexpr int WN = BN / 2, NT = WN / 8;
    constexpr int ATILE = TBM * ASTR;
    constexpr int BTILE = BK * BSTR;
    extern __shared__ __nv_bfloat16 smem[];
    __nv_bfloat16* sA = smem;
    __nv_bfloat16* sB = smem + 4 * ATILE;
    const uint32_t sAu = (uint32_t)__cvta_generic_to_shared(sA);
    const uint32_t sBu = (uint32_t)__cvta_generic_to_shared(sB);

    const int t = threadIdx.x;
    const int warp = t >> 5, lane = t & 31;
    const int wm = warp >> 1, wn = warp & 1;
    const int group = lane >> 2, tig = lane & 3;
    const int bm = blockIdx.y * TBM, bn = blockIdx.x * BN;

    float acc[MT][NT][4];
#pragma unroll
    for (int i = 0; i < MT; i++)
#pragma unroll
        for (int j = 0; j < NT; j++)
#pragma unroll
            for (int q = 0; q < 4; q++) acc[i][j][q] = 0.f;

    auto stage_load = [&](int kt, int stg) {
        const int k0 = kt * BK;
#pragma unroll
        for (int p = 0; p < 2; p++) {
            const __nv_bfloat16* Ag = p ? Alo : Ahi;
#pragma unroll
            for (int i = 0; i < MT; i++) {
                int c = t + i * 256;
                int row = c >> 2, colb = (c & 3) * 8;
                uint32_t dst = sAu + (uint32_t)(((stg * 2 + p) * ATILE + row * ASTR + colb) * 2);
                int grow = bm + row;
                const __nv_bfloat16* src = Ag + (size_t)(grow < M ? grow : 0) * K + k0 + colb;
                cpasync16(dst, src, grow < M ? 16 : 0);
            }
        }
        constexpr int CPROW = BN / 8;
        constexpr int NB = (BK * CPROW) / 256;
#pragma unroll
        for (int p = 0; p < 2; p++) {
            const __nv_bfloat16* Bg = p ? Blo : Bhi;
#pragma unroll
            for (int i = 0; i < NB; i++) {
                int c = t + i * 256;
                int row = c / CPROW, colb = (c % CPROW) * 8;
                uint32_t dst = sBu + (uint32_t)(((stg * 2 + p) * BTILE + row * BSTR + colb) * 2);
                cpasync16(dst, Bg + (size_t)(k0 + row) * N + bn + colb, 16);
            }
        }
    };

    auto compute = [&](int stg) {
#pragma unroll
        for (int ks = 0; ks < 2; ks++) {
            const int k = ks * 16;
            uint32_t Ah[MT][4], Al[MT][4];
#pragma unroll
            for (int mt = 0; mt < MT; mt++) {
                int row = wm * RPW + mt * 16 + (lane & 15);
                int col = k + 8 * (lane >> 4);
                ldmx4(Ah[mt], sAu + (uint32_t)(((stg * 2 + 0) * ATILE + row * ASTR + col) * 2));
                ldmx4(Al[mt], sAu + (uint32_t)(((stg * 2 + 1) * ATILE + row * ASTR + col) * 2));
            }
            const int brow = k + (lane & 7) + 8 * ((lane >> 3) & 1);
#pragma unroll
            for (int ntp = 0; ntp < NT / 2; ntp++) {
                int col = wn * WN + ntp * 16 + 8 * (lane >> 4);
                uint32_t Bh[4], Bl[4];
                ldmx4t(Bh, sBu + (uint32_t)(((stg * 2 + 0) * BTILE + brow * BSTR + col) * 2));
                ldmx4t(Bl, sBu + (uint32_t)(((stg * 2 + 1) * BTILE + brow * BSTR + col) * 2));
#pragma unroll
                for (int hf = 0; hf < 2; hf++) {
                    uint32_t bh2[2] = {Bh[2 * hf], Bh[2 * hf + 1]};
                    uint32_t bl2[2] = {Bl[2 * hf], Bl[2 * hf + 1]};
#pragma unroll
                    for (int mt = 0; mt < MT; mt++) {
                        float* a_ = acc[mt][2 * ntp + hf];
                        mma16(a_, Ah[mt], bh2);
                        mma16(a_, Ah[mt], bl2);
                        mma16(a_, Al[mt], bh2);
                    }
                }
            }
        }
    };

    const int KT = K / BK;
    stage_load(0, 0);
    asm volatile("cp.async.commit_group;");
    for (int kt = 0; kt < KT; kt++) {
        if (kt + 1 < KT) {
            stage_load(kt + 1, (kt + 1) & 1);
            asm volatile("cp.async.commit_group;");
            asm volatile("cp.async.wait_group 1;");
        } else {
            asm volatile("cp.async.wait_group 0;");
        }
        __syncthreads();
        compute(kt & 1);
        __syncthreads();
    }

    // epilogue: stores
#pragma unroll
    for (int mt = 0; mt < MT; mt++) {
        int r0 = bm + wm * RPW + mt * 16 + group;
        int r1 = r0 + 8;
#pragma unroll
        for (int nt = 0; nt < NT; nt++) {
            int c = bn + wn * WN + nt * 8 + tig * 2;
            if constexpr (WF32) {
                if (r0 < M) *(float2*)&C[(size_t)r0 * N + c] = make_float2(acc[mt][nt][0], acc[mt][nt][1]);
                if (r1 < M) *(float2*)&C[(size_t)r1 * N + c] = make_float2(acc[mt][nt][2], acc[mt][nt][3]);
            }
            if constexpr (WF16) {
                if (r0 < M) *(__half2*)&Fh[(size_t)r0 * N + c] = __floats2half2_rn(acc[mt][nt][0], acc[mt][nt][1]);
                if (r1 < M) *(__half2*)&Fh[(size_t)r1 * N + c] = __floats2half2_rn(acc[mt][nt][2], acc[mt][nt][3]);
            }
        }
    }

    if constexpr (ELRM == 4) {
        const int head = blockIdx.x * 2 + wn;
        float pel[MT][2] = {}, per_[MT][2] = {};
#pragma unroll
        for (int nt = 0; nt < NT; nt++) {
            int d = nt * 8 + tig * 2;
            float a0 = al[head * 64 + d], a1 = al[head * 64 + d + 1];
            float b0 = ar[head * 64 + d], b1 = ar[head * 64 + d + 1];
#pragma unroll
            for (int mt = 0; mt < MT; mt++) {
                pel[mt][0]  += acc[mt][nt][0] * a0 + acc[mt][nt][1] * a1;
                pel[mt][1]  += acc[mt][nt][2] * a0 + acc[mt][nt][3] * a1;
                per_[mt][0] += acc[mt][nt][0] * b0 + acc[mt][nt][1] * b1;
                per_[mt][1] += acc[mt][nt][2] * b0 + acc[mt][nt][3] * b1;
            }
        }
#pragma unroll
        for (int off = 1; off <= 2; off <<= 1) {
#pragma unroll
            for (int mt = 0; mt < MT; mt++)
#pragma unroll
                for (int rr = 0; rr < 2; rr++) {
                    pel[mt][rr]  += __shfl_xor_sync(0xffffffffu, pel[mt][rr], off);
                    per_[mt][rr] += __shfl_xor_sync(0xffffffffu, per_[mt][rr], off);
                }
        }
        if (tig == 0) {
#pragma unroll
            for (int mt = 0; mt < MT; mt++) {
                int r0 = bm + wm * RPW + mt * 16 + group;
                if (r0 < M)     { el[r0 * 4 + head] = pel[mt][0]; er[r0 * 4 + head] = per_[mt][0]; }
                if (r0 + 8 < M) { el[(r0 + 8) * 4 + head] = pel[mt][1]; er[(r0 + 8) * 4 + head] = per_[mt][1]; }
            }
        }
    }

    if constexpr (ELRM == 1) {
        float* sf = (float*)smem;
        float pel[MT][2] = {}, per_[MT][2] = {};
#pragma unroll
        for (int nt = 0; nt < NT; nt++) {
            int c = wn * WN + nt * 8 + tig * 2;
            float a0 = al[c], a1 = al[c + 1];
            float b0 = ar[c], b1 = ar[c + 1];
#pragma unroll
            for (int mt = 0; mt < MT; mt++) {
                pel[mt][0]  += acc[mt][nt][0] * a0 + acc[mt][nt][1] * a1;
                pel[mt][1]  += acc[mt][nt][2] * a0 + acc[mt][nt][3] * a1;
                per_[mt][0] += acc[mt][nt][0] * b0 + acc[mt][nt][1] * b1;
                per_[mt][1] += acc[mt][nt][2] * b0 + acc[mt][nt][3] * b1;
            }
        }
#pragma unroll
        for (int off = 1; off <= 2; off <<= 1) {
#pragma unroll
            for (int mt = 0; mt < MT; mt++)
#pragma unroll
                for (int rr = 0; rr < 2; rr++) {
                    pel[mt][rr]  += __shfl_xor_sync(0xffffffffu, pel[mt][rr], off);
                    per_[mt][rr] += __shfl_xor_sync(0xffffffffu, per_[mt][rr], off);
                }
        }
        __syncthreads();
        if (tig == 0) {
#pragma unroll
            for (int mt = 0; mt < MT; mt++)
#pragma unroll
                for (int rr = 0; rr < 2; rr++) {
                    int lrow = wm * RPW + mt * 16 + group + rr * 8;
                    sf[wn * (TBM * 2) + lrow * 2]     = pel[mt][rr];
                    sf[wn * (TBM * 2) + lrow * 2 + 1] = per_[mt][rr];
                }
        }
        __syncthreads();
        if (t < TBM) {
            int grow = bm + t;
            if (grow < M) {
                el[grow] = sf[t * 2]     + sf[TBM * 2 + t * 2];
                er[grow] = sf[t * 2 + 1] + sf[TBM * 2 + t * 2 + 1];
            }
        }
    }
}

// ---------------- BatchNorm ----------------
__global__ void bn_stats(const float* __restrict__ x, double* sum, double* sq, int M) {
    const int col = threadIdx.x & 63;
    const int rlane = threadIdx.x >> 6;
    double s = 0, q = 0;
    for (int r = blockIdx.x * 4 + rlane; r < M; r += gridDim.x * 4) {
        double v = x[(size_t)r * HF + col];
        s += v; q += v * v;
    }
    __shared__ double sh[2][256];
    sh[0][threadIdx.x] = s; sh[1][threadIdx.x] = q;
    __syncthreads();
    if (rlane == 0) {
#pragma unroll
        for (int i = 1; i < 4; i++) { s += sh[0][i * 64 + col]; q += sh[1][i * 64 + col]; }
        atomicAdd(&sum[col], s);
        atomicAdd(&sq[col], q);
    }
}

__global__ void bn_apply_bf(const float* __restrict__ x, const double* __restrict__ sum,
                            const double* __restrict__ sq, const float* __restrict__ g,
                            const float* __restrict__ b,
                            __nv_bfloat16* __restrict__ hi, __nv_bfloat16* __restrict__ lo,
                            int M) {
    int idx = blockIdx.x * blockDim.x + threadIdx.x;
    if (idx >= M * HF) return;
    int c = idx & 63;
    double mu = sum[c] / M;
    double var = sq[c] / M - mu * mu;
    float inv = rsqrtf((float)var + 1e-5f);
    float y = ((float)(x[idx] - mu)) * inv * g[c] + b[c];
    y = y > 0.f ? y : 0.01f * y;
    split_wr(y, &hi[idx], &lo[idx]);
}

// ---------------- fused GAT: ONE-PASS online softmax, 4-edge batches ----------------
template <int H, bool WB, bool FC>
__global__ void gat_agg(const __half* __restrict__ fh, const float* __restrict__ el,
                        const float* __restrict__ er, const int* __restrict__ rowptr,
                        const int* __restrict__ srcp, const float* __restrict__ bias,
                        const float* __restrict__ fcW, const float* __restrict__ fcb,
                        float* __restrict__ out,
                        __nv_bfloat16* __restrict__ ohi, __nv_bfloat16* __restrict__ olo) {
    constexpr int HD  = H * 64;
    constexpr int CPL = HD / 32;
    int node = (blockIdx.x * blockDim.x + threadIdx.x) >> 5;
    if (node >= NN) return;
    int lane = threadIdx.x & 31;
    int h  = (H == 4) ? (lane >> 3) : 0;
    int c0 = lane * CPL;
    int s0 = rowptr[node], s1 = rowptr[node + 1];
    float outv[CPL];
    if (s0 == s1) {
#pragma unroll
        for (int i = 0; i < CPL; i++) {
            float y = bias[c0 + i];
            outv[i] = y > 0.f ? y : 0.01f * y;
        }
    } else {
        float ern = er[node * H + h];
        int sfb = __ldg(&srcp[s0]);
        float m = -3.4e38f;
        float den = 0.f;
        float acc[CPL] = {};
        for (int e = s0; e < s1; e += 4) {
            int sx[4];
#pragma unroll
            for (int j = 0; j < 4; j++)
                sx[j] = (e + j) < s1 ? __ldg(&srcp[e + j]) : sfb;
            float vv[4];
#pragma unroll
            for (int j = 0; j < 4; j++) {
                float v = __ldg(&el[sx[j] * H + h]) + ern;
                v = v > 0.f ? v : 0.2f * v;
                vv[j] = (e + j) < s1 ? v : -3.4e38f;
            }
            if constexpr (CPL == 8) {
                uint4 raw[4];
#pragma unroll
                for (int j = 0; j < 4; j++)
                    raw[j] = *(const uint4*)(fh + (size_t)sx[j] * HD + c0);
                float bmax = fmaxf(fmaxf(vv[0], vv[1]), fmaxf(vv[2], vv[3]));
                if (bmax > m) {
                    float sc = __expf(m - bmax);
                    den *= sc;
#pragma unroll
                    for (int i = 0; i < CPL; i++) acc[i] *= sc;
                    m = bmax;
                }
#pragma unroll
                for (int j = 0; j < 4; j++) {
                    float ex = __expf(vv[j] - m);
                    den += ex;
                    const __half2* hp = (const __half2*)&raw[j];
#pragma unroll
                    for (int q = 0; q < 4; q++) {
                        float2 mv = __half22float2(hp[q]);
                        acc[2 * q]     = fmaf(ex, mv.x, acc[2 * q]);
                        acc[2 * q + 1] = fmaf(ex, mv.y, acc[2 * q + 1]);
                    }
                }
            } else {
                uint32_t raw[4];
#pragma unroll
                for (int j = 0; j < 4; j++)
                    raw[j] = *(const uint32_t*)(fh + (size_t)sx[j] * HD + c0);
                float bmax = fmaxf(fmaxf(vv[0], vv[1]), fmaxf(vv[2], vv[3]));
                if (bmax > m) {
                    float sc = __expf(m - bmax);
                    den *= sc;
#pragma unroll
                    for (int i = 0; i < CPL; i++) acc[i] *= sc;
                    m = bmax;
                }
#pragma unroll
                for (int j = 0; j < 4; j++) {
                    float ex = __expf(vv[j] - m);
                    den += ex;
                    float2 mv = __half22float2(*(const __half2*)&raw[j]);
                    acc[0] = fmaf(ex, mv.x, acc[0]);
                    acc[1] = fmaf(ex, mv.y, acc[1]);
                }
            }
        }
        float inv = 1.f / den;
#pragma unroll
        for (int i = 0; i < CPL; i++) {
            float y = acc[i] * inv + bias[c0 + i];
            outv[i] = y > 0.f ? y : 0.01f * y;
        }
    }
    if constexpr (FC) {
        float p0 = outv[0] * fcW[c0 * 2]     + outv[1] * fcW[(c0 + 1) * 2];
        float p1 = outv[0] * fcW[c0 * 2 + 1] + outv[1] * fcW[(c0 + 1) * 2 + 1];
#pragma unroll
        for (int off = 16; off; off >>= 1) {
            p0 += __shfl_xor_sync(0xffffffffu, p0, off);
            p1 += __shfl_xor_sync(0xffffffffu, p1, off);
        }
        if (lane == 0) {
            out[node * 2]     = p0 + fcb[0];
            out[node * 2 + 1] = p1 + fcb[1];
        }
    } else if constexpr (WB) {
        __nv_bfloat162 hp[CPL / 2], lp[CPL / 2];
#pragma unroll
        for (int j = 0; j < CPL / 2; j++) {
            float x = outv[2 * j], y = outv[2 * j + 1];
            __nv_bfloat162 h2 = __floats2bfloat162_rn(x, y);
            hp[j] = h2;
            lp[j] = __floats2bfloat162_rn(x - __bfloat162float(h2.x),
                                          y - __bfloat162float(h2.y));
        }
        size_t off = (size_t)node * HD + c0;
        *(uint4*)&ohi[off] = *(uint4*)hp;
        *(uint4*)&olo[off] = *(uint4*)lp;
    }
}

// ---------------- host ----------------
static inline int cdiv(long a, long b) { return (int)((a + b - 1) / b); }

extern "C" void kernel_launch(void* const* d_in, const int* in_sizes, int n_in,
                              void* d_out, int out_size) {
    const float* feat    = (const float*)d_in[0];
    const int*   src     = (const int*)  d_in[1];
    const int*   dst     = (const int*)  d_in[2];
    const float* enc1_W  = (const float*)d_in[3];
    const float* bn1_g   = (const float*)d_in[5];
    const float* bn1_b   = (const float*)d_in[6];
    const float* enc2_W  = (const float*)d_in[7];
    const float* bn2_g   = (const float*)d_in[9];
    const float* bn2_b   = (const float*)d_in[10];
    const float* gat0_W  = (const float*)d_in[11];
    const float* gat0_al = (const float*)d_in[12];
    const float* gat0_ar = (const float*)d_in[13];
    const float* gat0_b  = (const float*)d_in[14];
    const float* gatm_W  = (const float*)d_in[15];
    const float* gatm_al = (const float*)d_in[16];
    const float* gatm_ar = (const float*)d_in[17];
    const float* gatm_b  = (const float*)d_in[18];
    const float* gat4_W  = (const float*)d_in[19];
    const float* gat4_al = (const float*)d_in[20];
    const float* gat4_ar = (const float*)d_in[21];
    const float* gat4_b  = (const float*)d_in[22];
    const float* fc_W    = (const float*)d_in[23];
    const float* fc_b    = (const float*)d_in[24];
    float* out = (float*)d_out;

    float *tmp, *el, *er;
    __half* fh;
    __nv_bfloat16 *ahi, *alo, *whi, *wlo;
    double *bnstat;
    int *rowptr, *cnt, *cnt2, *srcp;
    cudaGetSymbolAddress((void**)&fh,     g_fh);
    cudaGetSymbolAddress((void**)&tmp,    g_t);
    cudaGetSymbolAddress((void**)&ahi,    g_ahi);
    cudaGetSymbolAddress((void**)&alo,    g_alo);
    cudaGetSymbolAddress((void**)&whi,    g_whi);
    cudaGetSymbolAddress((void**)&wlo,    g_wlo);
    cudaGetSymbolAddress((void**)&el,     g_el);
    cudaGetSymbolAddress((void**)&er,     g_er);
    cudaGetSymbolAddress((void**)&bnstat, g_bnstat);
    cudaGetSymbolAddress((void**)&rowptr, g_rowptr);
    cudaGetSymbolAddress((void**)&cnt,    g_cnt);
    cudaGetSymbolAddress((void**)&cnt2,   g_cnt2);
    cudaGetSymbolAddress((void**)&srcp,   g_srcp);

    const int SM64_128 = (4 * 64 * 40 + 4 * 32 * (128 + 8)) * 2;  // 55296
    const int SM64     = (4 * 64 * 40 + 4 * 32 * (64 + 8)) * 2;   // 38912
    cudaFuncSetAttribute((const void*)gemm3<64, 128, 4, true, false>,
                         cudaFuncAttributeMaxDynamicSharedMemorySize, SM64_128);
    cudaFuncSetAttribute((const void*)gemm3<64, 64, 0, false, true>,
                         cudaFuncAttributeMaxDynamicSharedMemorySize, SM64);
    cudaFuncSetAttribute((const void*)gemm3<64, 64, 1, true, false>,
                         cudaFuncAttributeMaxDynamicSharedMemorySize, SM64);

    const int MB64 = cdiv(NN, 64);   // 313
    const int WARP_BLOCKS = cdiv((long)NN * 32, 256);

    // ---- fork/join: CSR chain on a side stream, overlapped with encoder ----
    cudaStream_t s2;
    cudaStreamCreate(&s2);
    cudaEvent_t ev1, ev2;
    cudaEventCreateWithFlags(&ev1, cudaEventDisableTiming);
    cudaEventCreateWithFlags(&ev2, cudaEventDisableTiming);

    // main: zero counters + split feat
    split_feat_zero<<<cdiv((long)NN * 64, 256), 256>>>(feat, ahi, alo, cnt, cnt2, bnstat);
    cudaEventRecord(ev1, 0);

    // side: CSR build (depends only on zeroed cnt/cnt2)
    cudaStreamWaitEvent(s2, ev1, 0);
    hist_k<<<cdiv(EE, 256), 256, 0, s2>>>(dst, cnt);
    scan_k<<<1, 1024, 0, s2>>>(cnt, rowptr);
    scatter_k<<<cdiv(EE, 256), 256, 0, s2>>>(src, dst, rowptr, cnt2, srcp);
    cudaEventRecord(ev2, s2);

    // main: weights + encoder (independent of CSR)
    splitW_all<<<cdiv(W_TOTAL, 256), 256>>>(enc1_W, enc2_W, gat0_W, gatm_W, gat4_W, whi, wlo);
    gemm3<64, 64, 0, false, true><<<dim3(1, MB64), 256, SM64>>>(
        ahi, alo, whi + W_ENC1, wlo + W_ENC1, tmp, nullptr, NN, HF, 64,
        nullptr, nullptr, nullptr, nullptr);
    bn_stats<<<120, 256>>>(tmp, bnstat, bnstat + HF, NN);
    bn_apply_bf<<<cdiv((long)NN * HF, 256), 256>>>(tmp, bnstat, bnstat + HF,
                                                   bn1_g, bn1_b, ahi, alo, NN);
    gemm3<64, 64, 0, false, true><<<dim3(1, MB64), 256, SM64>>>(
        ahi, alo, whi + W_ENC2, wlo + W_ENC2, tmp, nullptr, NN, HF, 64,
        nullptr, nullptr, nullptr, nullptr);
    bn_stats<<<120, 256>>>(tmp, bnstat + 2 * HF, bnstat + 3 * HF, NN);
    bn_apply_bf<<<cdiv((long)NN * HF, 256), 256>>>(tmp, bnstat + 2 * HF, bnstat + 3 * HF,
                                                   bn2_g, bn2_b, ahi, alo, NN);

    // gat0 GEMM does not need CSR; join before first gat_agg
    gemm3<64, 128, 4, true, false><<<dim3(2, MB64), 256, SM64_128>>>(
        ahi, alo, whi + W_GAT0, wlo + W_GAT0, nullptr, fh, NN, HDMAX, 64,
        gat0_al, gat0_ar, el, er);
    cudaStreamWaitEvent(0, ev2, 0);
    gat_agg<4, true, false><<<WARP_BLOCKS, 256>>>(fh, el, er, rowptr, srcp, gat0_b,
                                                  nullptr, nullptr, nullptr, ahi, alo);
    for (int i = 0; i < 3; i++) {
        gemm3<64, 128, 4, true, false><<<dim3(2, MB64), 256, SM64_128>>>(
            ahi, alo, whi + W_GATM + (size_t)i * HDMAX * HDMAX,
            wlo + W_GATM + (size_t)i * HDMAX * HDMAX, nullptr, fh, NN, HDMAX, HDMAX,
            gatm_al + i * NHEADS * HF, gatm_ar + i * NHEADS * HF, el, er);
        gat_agg<4, true, false><<<WARP_BLOCKS, 256>>>(fh, el, er, rowptr, srcp,
                                                      gatm_b + i * HDMAX,
                                                      nullptr, nullptr, nullptr, ahi, alo);
    }
    gemm3<64, 64, 1, true, false><<<dim3(1, MB64), 256, SM64>>>(
        ahi, alo, whi + W_GAT4, wlo + W_GAT4, nullptr, fh, NN, HF, HDMAX,
        gat4_al, gat4_ar, el, er);
    gat_agg<1, false, true><<<WARP_BLOCKS, 256>>>(fh, el, er, rowptr, srcp, gat4_b,
                                                  fc_W, fc_b, out, nullptr, nullptr);

    cudaEventDestroy(ev1);
    cudaEventDestroy(ev2);
    cudaStreamDestroy(s2);
}